// round 3
// baseline (speedup 1.0000x reference)
#include <cuda_runtime.h>
#include <mma.h>

using namespace nvcuda;

// Problem constants
#define B_    256
#define S_    64
#define DIN_  1024
#define H_    512
#define H3_   1536
#define E_    512
#define M_    (S_ * B_)   // 16384 rows (t*B + b)

// Scratch (device globals; no runtime allocation allowed)
__device__ float g_X[(size_t)M_ * DIN_];        // [t*B+b][1024]
__device__ float g_GI[2][(size_t)M_ * H3_];     // input-transform, per dir, NO bias
__device__ float g_Hbuf[2][(size_t)M_ * H_];    // GRU outputs per original time index

// ---------------------------------------------------------------------------
// Kernel 1: gather slot embedding + concat value embeds -> X[t*B+b][1024]
// ---------------------------------------------------------------------------
__global__ void build_x_kernel(const int* __restrict__ slot_ids,
                               const float* __restrict__ value_embeds,
                               const float* __restrict__ embed_table) {
    int m = blockIdx.x;            // = t*B + b
    int t = m >> 8;                // / 256
    int b = m & 255;
    int c4 = threadIdx.x;          // float4 column 0..255 (1024 floats)
    float4 v;
    if (c4 < 64) {                 // slot embedding: 256 floats
        int sid = slot_ids[b * S_ + t];
        v = ((const float4*)embed_table)[(size_t)sid * 64 + c4];
    } else {                       // value embedding: 768 floats
        v = ((const float4*)value_embeds)[(size_t)(b * S_ + t) * 192 + (c4 - 64)];
    }
    ((float4*)g_X)[(size_t)m * 256 + c4] = v;
}

// ---------------------------------------------------------------------------
// Kernel 2: input GEMM  GI[dir] = X @ W_ih[dir]^T   (M=16384, N=1536, K=1024)
// Block tile 128x64, 8 warps (4x2), warp tile 32x32, K-step 32, tf32 wmma.
// ---------------------------------------------------------------------------
__global__ void input_gemm_kernel(const float* __restrict__ Wf,
                                  const float* __restrict__ Wb) {
    const float* __restrict__ W = blockIdx.z ? Wb : Wf;
    float* __restrict__ C = g_GI[blockIdx.z];
    const int n0 = blockIdx.x * 64;
    const int m0 = blockIdx.y * 128;

    __shared__ __align__(16) float As[128][32];
    __shared__ __align__(16) float Bs[64][40];   // pad 40 keeps 16B alignment

    const int tid  = threadIdx.x;
    const int warp = tid >> 5;
    const int wm = (warp & 3) * 32;
    const int wn = (warp >> 2) * 32;

    wmma::fragment<wmma::accumulator, 16, 16, 8, float> acc[2][2];
    #pragma unroll
    for (int i = 0; i < 2; i++)
        #pragma unroll
        for (int j = 0; j < 2; j++)
            wmma::fill_fragment(acc[i][j], 0.0f);

    for (int k0 = 0; k0 < DIN_; k0 += 32) {
        #pragma unroll
        for (int i = 0; i < 4; i++) {            // A: 128x32 = 1024 float4
            int idx = i * 256 + tid;
            int r = idx >> 3, c = (idx & 7) << 2;
            float4 v = *(const float4*)&g_X[(size_t)(m0 + r) * DIN_ + k0 + c];
            *(float4*)&As[r][c] = v;
        }
        #pragma unroll
        for (int i = 0; i < 2; i++) {            // B: 64x32 = 512 float4
            int idx = i * 256 + tid;
            int r = idx >> 3, c = (idx & 7) << 2;
            float4 v = *(const float4*)&W[(size_t)(n0 + r) * DIN_ + k0 + c];
            *(float4*)&Bs[r][c] = v;
        }
        __syncthreads();

        #pragma unroll
        for (int kk = 0; kk < 32; kk += 8) {
            wmma::fragment<wmma::matrix_a, 16, 16, 8, wmma::precision::tf32, wmma::row_major> a0, a1;
            wmma::fragment<wmma::matrix_b, 16, 16, 8, wmma::precision::tf32, wmma::col_major> b0, b1;
            wmma::load_matrix_sync(a0, &As[wm][kk], 32);
            wmma::load_matrix_sync(a1, &As[wm + 16][kk], 32);
            wmma::load_matrix_sync(b0, &Bs[wn][kk], 40);
            wmma::load_matrix_sync(b1, &Bs[wn + 16][kk], 40);
            #pragma unroll
            for (int i = 0; i < a0.num_elements; i++) {
                a0.x[i] = wmma::__float_to_tf32(a0.x[i]);
                a1.x[i] = wmma::__float_to_tf32(a1.x[i]);
            }
            #pragma unroll
            for (int i = 0; i < b0.num_elements; i++) {
                b0.x[i] = wmma::__float_to_tf32(b0.x[i]);
                b1.x[i] = wmma::__float_to_tf32(b1.x[i]);
            }
            wmma::mma_sync(acc[0][0], a0, b0, acc[0][0]);
            wmma::mma_sync(acc[0][1], a0, b1, acc[0][1]);
            wmma::mma_sync(acc[1][0], a1, b0, acc[1][0]);
            wmma::mma_sync(acc[1][1], a1, b1, acc[1][1]);
        }
        __syncthreads();
    }

    #pragma unroll
    for (int i = 0; i < 2; i++)
        #pragma unroll
        for (int j = 0; j < 2; j++)
            wmma::store_matrix_sync(&C[(size_t)(m0 + wm + i * 16) * H3_ + n0 + wn + j * 16],
                                    acc[i][j], H3_, wmma::mem_row_major);
}

// ---------------------------------------------------------------------------
// Kernel 3: one GRU step for both directions.
// Block tile: 64 batch x 32 hidden, all 3 gates (GEMM M=64,N=96,K=512) + gates.
// 8 warps: 4(M) x 2(J), each warp 16x16 per gate.
// ---------------------------------------------------------------------------
__global__ void gru_step_kernel(int tau,
                                const float* __restrict__ Whh_f,
                                const float* __restrict__ Whh_b,
                                const float* __restrict__ bih_f,
                                const float* __restrict__ bhh_f,
                                const float* __restrict__ bih_b,
                                const float* __restrict__ bhh_b) {
    const int dir = blockIdx.z;
    const int j0 = blockIdx.x * 32;
    const int b0 = blockIdx.y * 64;
    const float* __restrict__ Whh = dir ? Whh_b : Whh_f;
    const float* __restrict__ bih = dir ? bih_b : bih_f;
    const float* __restrict__ bhh = dir ? bhh_b : bhh_f;
    float* __restrict__ GI  = g_GI[dir];
    float* __restrict__ Hst = g_Hbuf[dir];

    const int row_store = dir ? (S_ - 1 - tau) : tau;           // also the x/GI index
    const int row_prev  = dir ? (S_ - tau)     : (tau - 1);
    const float* __restrict__ hprev =
        (tau > 0) ? &Hst[(size_t)row_prev * B_ * H_] : nullptr; // [256][512]

    __shared__ __align__(16) union SmemU {
        struct { float As[64][32]; float Bs[3][32][40]; } ld;
        float gh[3][64][32];
    } sm;

    const int tid  = threadIdx.x;
    const int warp = tid >> 5;
    const int wm = (warp & 3) * 16;   // rows 0..63
    const int wj = (warp >> 2) * 16;  // j 0..31

    if (tau > 0) {
        wmma::fragment<wmma::accumulator, 16, 16, 8, float> acc[3];
        #pragma unroll
        for (int g = 0; g < 3; g++) wmma::fill_fragment(acc[g], 0.0f);

        for (int k0 = 0; k0 < H_; k0 += 32) {
            #pragma unroll
            for (int i = 0; i < 2; i++) {        // A: 64x32 = 512 float4
                int idx = i * 256 + tid;
                int r = idx >> 3, c = (idx & 7) << 2;
                float4 v = *(const float4*)&hprev[(size_t)(b0 + r) * H_ + k0 + c];
                *(float4*)&sm.ld.As[r][c] = v;
            }
            #pragma unroll
            for (int g = 0; g < 3; g++) {        // B: 3 x 32x32 rows of Whh
                int r = tid >> 3, c = (tid & 7) << 2;
                float4 v = *(const float4*)&Whh[(size_t)(g * H_ + j0 + r) * H_ + k0 + c];
                *(float4*)&sm.ld.Bs[g][r][c] = v;
            }
            __syncthreads();

            #pragma unroll
            for (int kk = 0; kk < 32; kk += 8) {
                wmma::fragment<wmma::matrix_a, 16, 16, 8, wmma::precision::tf32, wmma::row_major> a;
                wmma::load_matrix_sync(a, &sm.ld.As[wm][kk], 32);
                #pragma unroll
                for (int i = 0; i < a.num_elements; i++)
                    a.x[i] = wmma::__float_to_tf32(a.x[i]);
                #pragma unroll
                for (int g = 0; g < 3; g++) {
                    wmma::fragment<wmma::matrix_b, 16, 16, 8, wmma::precision::tf32, wmma::col_major> bf;
                    wmma::load_matrix_sync(bf, &sm.ld.Bs[g][wj][kk], 40);
                    #pragma unroll
                    for (int i = 0; i < bf.num_elements; i++)
                        bf.x[i] = wmma::__float_to_tf32(bf.x[i]);
                    wmma::mma_sync(acc[g], a, bf, acc[g]);
                }
            }
            __syncthreads();
        }
        #pragma unroll
        for (int g = 0; g < 3; g++)
            wmma::store_matrix_sync(&sm.gh[g][wm][wj], acc[g], 32, wmma::mem_row_major);
        __syncthreads();
    }

    // Gate epilogue: 64x32 elements, 8 per thread
    const size_t gi_base = (size_t)(row_store * B_) * H3_;
    const size_t h_base  = (size_t)(row_store * B_) * H_;
    #pragma unroll
    for (int i = tid; i < 64 * 32; i += 256) {
        int r = i >> 5, c = i & 31;
        int bb = b0 + r;
        int j  = j0 + c;
        float hr = 0.f, hz = 0.f, hn = 0.f, hp = 0.f;
        if (tau > 0) {
            hr = sm.gh[0][r][c];
            hz = sm.gh[1][r][c];
            hn = sm.gh[2][r][c];
            hp = hprev[(size_t)bb * H_ + j];
        }
        size_t girow = gi_base + (size_t)bb * H3_;
        float ir  = GI[girow + j]            + bih[j];
        float iz  = GI[girow + H_ + j]       + bih[H_ + j];
        float inn = GI[girow + 2 * H_ + j]   + bih[2 * H_ + j];
        hr += bhh[j];
        hz += bhh[H_ + j];
        hn += bhh[2 * H_ + j];
        float rg = 1.f / (1.f + expf(-(ir + hr)));
        float zg = 1.f / (1.f + expf(-(iz + hz)));
        float ng = tanhf(inn + rg * hn);
        float hnew = (1.f - zg) * ng + zg * hp;
        Hst[h_base + (size_t)bb * H_ + j] = hnew;
    }
}

// ---------------------------------------------------------------------------
// Kernel 4: projection  out[b][s][e] = concat(Hf[s*B+b], Hb[s*B+b]) @ Wproj^T
// M=16384, N=512, K=1024 (K<512 from Hf, else Hb). Output written transposed
// to [B][S][E] via strided store (tile rows = consecutive b for fixed s).
// ---------------------------------------------------------------------------
__global__ void proj_gemm_kernel(const float* __restrict__ Wp,
                                 float* __restrict__ out) {
    const int n0 = blockIdx.x * 64;
    const int m0 = blockIdx.y * 128;

    __shared__ __align__(16) float As[128][32];
    __shared__ __align__(16) float Bs[64][40];

    const int tid  = threadIdx.x;
    const int warp = tid >> 5;
    const int wm = (warp & 3) * 32;
    const int wn = (warp >> 2) * 32;

    wmma::fragment<wmma::accumulator, 16, 16, 8, float> acc[2][2];
    #pragma unroll
    for (int i = 0; i < 2; i++)
        #pragma unroll
        for (int j = 0; j < 2; j++)
            wmma::fill_fragment(acc[i][j], 0.0f);

    for (int k0 = 0; k0 < 2 * H_; k0 += 32) {
        const float* __restrict__ Asrc = (k0 < H_) ? g_Hbuf[0] : g_Hbuf[1];
        const int kc = (k0 < H_) ? k0 : (k0 - H_);
        #pragma unroll
        for (int i = 0; i < 4; i++) {            // A: 128x32
            int idx = i * 256 + tid;
            int r = idx >> 3, c = (idx & 7) << 2;
            float4 v = *(const float4*)&Asrc[(size_t)(m0 + r) * H_ + kc + c];
            *(float4*)&As[r][c] = v;
        }
        #pragma unroll
        for (int i = 0; i < 2; i++) {            // B: 64x32 rows of Wproj
            int idx = i * 256 + tid;
            int r = idx >> 3, c = (idx & 7) << 2;
            float4 v = *(const float4*)&Wp[(size_t)(n0 + r) * (2 * H_) + k0 + c];
            *(float4*)&Bs[r][c] = v;
        }
        __syncthreads();

        #pragma unroll
        for (int kk = 0; kk < 32; kk += 8) {
            wmma::fragment<wmma::matrix_a, 16, 16, 8, wmma::precision::tf32, wmma::row_major> a0, a1;
            wmma::fragment<wmma::matrix_b, 16, 16, 8, wmma::precision::tf32, wmma::col_major> b0, b1;
            wmma::load_matrix_sync(a0, &As[wm][kk], 32);
            wmma::load_matrix_sync(a1, &As[wm + 16][kk], 32);
            wmma::load_matrix_sync(b0, &Bs[wn][kk], 40);
            wmma::load_matrix_sync(b1, &Bs[wn + 16][kk], 40);
            #pragma unroll
            for (int i = 0; i < a0.num_elements; i++) {
                a0.x[i] = wmma::__float_to_tf32(a0.x[i]);
                a1.x[i] = wmma::__float_to_tf32(a1.x[i]);
            }
            #pragma unroll
            for (int i = 0; i < b0.num_elements; i++) {
                b0.x[i] = wmma::__float_to_tf32(b0.x[i]);
                b1.x[i] = wmma::__float_to_tf32(b1.x[i]);
            }
            wmma::mma_sync(acc[0][0], a0, b0, acc[0][0]);
            wmma::mma_sync(acc[0][1], a0, b1, acc[0][1]);
            wmma::mma_sync(acc[1][0], a1, b0, acc[1][0]);
            wmma::mma_sync(acc[1][1], a1, b1, acc[1][1]);
        }
        __syncthreads();
    }

    // Output mapping: row m = s*B + b  ->  out[(b*S + s)*E + n]
    const int s    = m0 >> 8;      // m0 / 256
    const int brow = m0 & 255;
    float* __restrict__ Cb = out + ((size_t)brow * S_ + s) * E_;
    const int ldc = S_ * E_;       // consecutive tile rows advance b by 1
    #pragma unroll
    for (int i = 0; i < 2; i++)
        #pragma unroll
        for (int j = 0; j < 2; j++)
            wmma::store_matrix_sync(&Cb[(size_t)(wm + i * 16) * ldc + n0 + wn + j * 16],
                                    acc[i][j], ldc, wmma::mem_row_major);
}

// ---------------------------------------------------------------------------
extern "C" void kernel_launch(void* const* d_in, const int* in_sizes, int n_in,
                              void* d_out, int out_size) {
    const int*   slot_ids = (const int*)d_in[0];
    const float* value    = (const float*)d_in[1];
    const float* table    = (const float*)d_in[2];
    const float* Wih_f    = (const float*)d_in[3];
    const float* Whh_f    = (const float*)d_in[4];
    const float* bih_f    = (const float*)d_in[5];
    const float* bhh_f    = (const float*)d_in[6];
    const float* Wih_b    = (const float*)d_in[7];
    const float* Whh_b    = (const float*)d_in[8];
    const float* bih_b    = (const float*)d_in[9];
    const float* bhh_b    = (const float*)d_in[10];
    const float* Wproj    = (const float*)d_in[11];
    float* out = (float*)d_out;

    build_x_kernel<<<M_, 256>>>(slot_ids, value, table);
    input_gemm_kernel<<<dim3(H3_ / 64, M_ / 128, 2), 256>>>(Wih_f, Wih_b);
    for (int tau = 0; tau < S_; tau++) {
        gru_step_kernel<<<dim3(H_ / 32, B_ / 64, 2), 256>>>(
            tau, Whh_f, Whh_b, bih_f, bhh_f, bih_b, bhh_b);
    }
    proj_gemm_kernel<<<dim3(E_ / 64, M_ / 128), 256>>>(Wproj, out);
}

// round 5
// speedup vs baseline: 1.3154x; 1.3154x over previous
#include <cuda_runtime.h>
#include <mma.h>

using namespace nvcuda;

// Problem constants
#define B_    256
#define S_    64
#define DIN_  1024
#define H_    512
#define H3_   1536
#define E_    512
#define M_    (S_ * B_)   // 16384 rows (t*B + b)

#define NCTA  128         // persistent recurrence kernel grid size

// Scratch (device globals; no runtime allocation allowed)
__device__ float g_X[(size_t)M_ * DIN_];        // [t*B+b][1024]
__device__ float g_GI[2][(size_t)M_ * H3_];     // input-transform, per dir, NO bias
__device__ float g_Hbuf[2][(size_t)M_ * H_];    // GRU outputs per original time index

// Grid barrier state (zero-initialized at module load; invariant: count
// returns to 0 after every barrier, gen monotonically increases -> replay-safe)
__device__ volatile unsigned g_bar_count = 0;
__device__ volatile unsigned g_bar_gen   = 0;

__device__ __forceinline__ void grid_barrier() {
    __syncthreads();
    if (threadIdx.x == 0) {
        __threadfence();
        unsigned gen = g_bar_gen;
        unsigned arrived = atomicAdd((unsigned*)&g_bar_count, 1u);
        if (arrived == NCTA - 1) {
            g_bar_count = 0;
            __threadfence();
            atomicAdd((unsigned*)&g_bar_gen, 1u);
        } else {
            while (g_bar_gen == gen) { __nanosleep(32); }
            __threadfence();
        }
    }
    __syncthreads();
}

// ---------------------------------------------------------------------------
// Kernel 1: gather slot embedding + concat value embeds -> X[t*B+b][1024]
// ---------------------------------------------------------------------------
__global__ void build_x_kernel(const int* __restrict__ slot_ids,
                               const float* __restrict__ value_embeds,
                               const float* __restrict__ embed_table) {
    int m = blockIdx.x;            // = t*B + b
    int t = m >> 8;                // / 256
    int b = m & 255;
    int c4 = threadIdx.x;          // float4 column 0..255 (1024 floats)
    float4 v;
    if (c4 < 64) {                 // slot embedding: 256 floats
        int sid = slot_ids[b * S_ + t];
        v = ((const float4*)embed_table)[(size_t)sid * 64 + c4];
    } else {                       // value embedding: 768 floats
        v = ((const float4*)value_embeds)[(size_t)(b * S_ + t) * 192 + (c4 - 64)];
    }
    ((float4*)g_X)[(size_t)m * 256 + c4] = v;
}

// ---------------------------------------------------------------------------
// Kernel 2: input GEMM  GI[dir] = X @ W_ih[dir]^T   (M=16384, N=1536, K=1024)
// Block tile 128x128, 8 warps (2Mx4N), warp tile 64x32, K-step 32, tf32 wmma.
// tf32 conversion done once at SMEM staging (not per fragment).
// ---------------------------------------------------------------------------
__global__ __launch_bounds__(256)
void input_gemm_kernel(const float* __restrict__ Wf,
                       const float* __restrict__ Wb) {
    const float* __restrict__ W = blockIdx.z ? Wb : Wf;
    float* __restrict__ C = g_GI[blockIdx.z];
    const int n0 = blockIdx.x * 128;
    const int m0 = blockIdx.y * 128;

    __shared__ __align__(16) float As[128][40];
    __shared__ __align__(16) float Bs[128][40];

    const int tid  = threadIdx.x;
    const int warp = tid >> 5;
    const int wm = (warp & 1) * 64;
    const int wn = (warp >> 1) * 32;

    wmma::fragment<wmma::accumulator, 16, 16, 8, float> acc[4][2];
    #pragma unroll
    for (int i = 0; i < 4; i++)
        #pragma unroll
        for (int j = 0; j < 2; j++)
            wmma::fill_fragment(acc[i][j], 0.0f);

    for (int k0 = 0; k0 < DIN_; k0 += 32) {
        #pragma unroll
        for (int i = 0; i < 4; i++) {            // A: 128x32 = 1024 float4
            int idx = i * 256 + tid;
            int r = idx >> 3, c = (idx & 7) << 2;
            float4 v = *(const float4*)&g_X[(size_t)(m0 + r) * DIN_ + k0 + c];
            v.x = wmma::__float_to_tf32(v.x); v.y = wmma::__float_to_tf32(v.y);
            v.z = wmma::__float_to_tf32(v.z); v.w = wmma::__float_to_tf32(v.w);
            *(float4*)&As[r][c] = v;
        }
        #pragma unroll
        for (int i = 0; i < 4; i++) {            // B: 128x32 = 1024 float4
            int idx = i * 256 + tid;
            int r = idx >> 3, c = (idx & 7) << 2;
            float4 v = *(const float4*)&W[(size_t)(n0 + r) * DIN_ + k0 + c];
            v.x = wmma::__float_to_tf32(v.x); v.y = wmma::__float_to_tf32(v.y);
            v.z = wmma::__float_to_tf32(v.z); v.w = wmma::__float_to_tf32(v.w);
            *(float4*)&Bs[r][c] = v;
        }
        __syncthreads();

        #pragma unroll
        for (int kk = 0; kk < 32; kk += 8) {
            wmma::fragment<wmma::matrix_a, 16, 16, 8, wmma::precision::tf32, wmma::row_major> a[4];
            wmma::fragment<wmma::matrix_b, 16, 16, 8, wmma::precision::tf32, wmma::col_major> b[2];
            #pragma unroll
            for (int i = 0; i < 4; i++)
                wmma::load_matrix_sync(a[i], &As[wm + i * 16][kk], 40);
            #pragma unroll
            for (int j = 0; j < 2; j++)
                wmma::load_matrix_sync(b[j], &Bs[wn + j * 16][kk], 40);
            #pragma unroll
            for (int i = 0; i < 4; i++)
                #pragma unroll
                for (int j = 0; j < 2; j++)
                    wmma::mma_sync(acc[i][j], a[i], b[j], acc[i][j]);
        }
        __syncthreads();
    }

    #pragma unroll
    for (int i = 0; i < 4; i++)
        #pragma unroll
        for (int j = 0; j < 2; j++)
            wmma::store_matrix_sync(&C[(size_t)(m0 + wm + i * 16) * H3_ + n0 + wn + j * 16],
                                    acc[i][j], H3_, wmma::mem_row_major);
}

// ---------------------------------------------------------------------------
// Kernel 3: PERSISTENT bidirectional GRU recurrence. One launch, 64 steps,
// grid-wide barrier between steps. 128 CTAs (1/SM):
//   cta -> dir (2) x j-slice of 16 hidden cols (32) x batch half of 128 (2)
// Whh slice (3 gates x 16 j x 512 k, tf32) resident in SMEM for all steps.
// Per step: GEMM M=128, N=48, K=512 + fused gate epilogue.
// ---------------------------------------------------------------------------
#define PSMEM_FLOATS (3 * 16 * 520 + 3 * 128 * 16)
#define PSMEM_BYTES  (PSMEM_FLOATS * 4)

__global__ __launch_bounds__(256, 1)
void gru_persistent_kernel(const float* __restrict__ Whh_f,
                           const float* __restrict__ Whh_b,
                           const float* __restrict__ bih_f,
                           const float* __restrict__ bhh_f,
                           const float* __restrict__ bih_b,
                           const float* __restrict__ bhh_b) {
    extern __shared__ float smem_raw[];
    float (*Wsm)[16][520]   = (float(*)[16][520])smem_raw;          // [3][16][520]
    float* ubase            = smem_raw + 3 * 16 * 520;
    float (*Asm)[40]        = (float(*)[40])ubase;                  // [128][40]
    float (*GHsm)[128][16]  = (float(*)[128][16])ubase;             // [3][128][16]

    const int cta = blockIdx.x;
    const int dir = cta >> 6;
    const int rem = cta & 63;
    const int j0  = (rem >> 1) * 16;
    const int b0  = (rem & 1) * 128;

    const int tid  = threadIdx.x;
    const int warp = tid >> 5;

    const float* __restrict__ Whh = dir ? Whh_b : Whh_f;
    const float* __restrict__ bih = dir ? bih_b : bih_f;
    const float* __restrict__ bhh = dir ? bhh_b : bhh_f;
    float* __restrict__ GI  = g_GI[dir];
    float* __restrict__ Hst = g_Hbuf[dir];

    // Load this CTA's Whh slice into SMEM once (tf32-converted).
    // 3 gates x 16 j x 512 k = 6144 float4.
    for (int idx = tid; idx < 6144; idx += 256) {
        int row = idx >> 7;           // 0..47
        int c4  = idx & 127;
        int g = row >> 4, jl = row & 15;
        float4 v = *(const float4*)&Whh[((size_t)(g * H_ + j0 + jl)) * H_ + (c4 << 2)];
        v.x = wmma::__float_to_tf32(v.x); v.y = wmma::__float_to_tf32(v.y);
        v.z = wmma::__float_to_tf32(v.z); v.w = wmma::__float_to_tf32(v.w);
        *(float4*)&Wsm[g][jl][c4 << 2] = v;
    }
    __syncthreads();

    for (int tau = 0; tau < S_; tau++) {
        const int row_store = dir ? (S_ - 1 - tau) : tau;
        const float* __restrict__ hprev = nullptr;

        if (tau > 0) {
            const int row_prev = dir ? (S_ - tau) : (tau - 1);
            hprev = &Hst[(size_t)row_prev * B_ * H_];

            wmma::fragment<wmma::accumulator, 16, 16, 8, float> acc[3];
            #pragma unroll
            for (int g = 0; g < 3; g++) wmma::fill_fragment(acc[g], 0.0f);

            for (int k0 = 0; k0 < H_; k0 += 32) {
                #pragma unroll
                for (int i = 0; i < 4; i++) {    // A: 128x32 = 1024 float4  (BUGFIX: was 2)
                    int idx = i * 256 + tid;
                    int r = idx >> 3, c = (idx & 7) << 2;
                    float4 v = *(const float4*)&hprev[(size_t)(b0 + r) * H_ + k0 + c];
                    v.x = wmma::__float_to_tf32(v.x); v.y = wmma::__float_to_tf32(v.y);
                    v.z = wmma::__float_to_tf32(v.z); v.w = wmma::__float_to_tf32(v.w);
                    *(float4*)&Asm[r][c] = v;
                }
                __syncthreads();

                #pragma unroll
                for (int kk = 0; kk < 32; kk += 8) {
                    wmma::fragment<wmma::matrix_a, 16, 16, 8, wmma::precision::tf32, wmma::row_major> a;
                    wmma::load_matrix_sync(a, &Asm[warp * 16][kk], 40);
                    #pragma unroll
                    for (int g = 0; g < 3; g++) {
                        wmma::fragment<wmma::matrix_b, 16, 16, 8, wmma::precision::tf32, wmma::col_major> bf;
                        wmma::load_matrix_sync(bf, &Wsm[g][0][k0 + kk], 520);
                        wmma::mma_sync(acc[g], a, bf, acc[g]);
                    }
                }
                __syncthreads();
            }
            #pragma unroll
            for (int g = 0; g < 3; g++)
                wmma::store_matrix_sync(&GHsm[g][warp * 16][0], acc[g], 16, wmma::mem_row_major);
            __syncthreads();
        }

        // Gate epilogue: 128 rows x 16 j = 2048 elements, 8 per thread
        const size_t gi_base = (size_t)(row_store * B_) * H3_;
        const size_t h_base  = (size_t)(row_store * B_) * H_;
        #pragma unroll
        for (int i = tid; i < 128 * 16; i += 256) {
            int r = i >> 4, c = i & 15;
            int bb = b0 + r;
            int j  = j0 + c;
            float hr = 0.f, hz = 0.f, hn = 0.f, hp = 0.f;
            if (tau > 0) {
                hr = GHsm[0][r][c];
                hz = GHsm[1][r][c];
                hn = GHsm[2][r][c];
                hp = hprev[(size_t)bb * H_ + j];
            }
            size_t girow = gi_base + (size_t)bb * H3_;
            float ir  = GI[girow + j]          + bih[j];
            float iz  = GI[girow + H_ + j]     + bih[H_ + j];
            float inn = GI[girow + 2 * H_ + j] + bih[2 * H_ + j];
            hr += bhh[j];
            hz += bhh[H_ + j];
            hn += bhh[2 * H_ + j];
            float rg = 1.f / (1.f + expf(-(ir + hr)));
            float zg = 1.f / (1.f + expf(-(iz + hz)));
            float ng = tanhf(inn + rg * hn);
            float hnew = (1.f - zg) * ng + zg * hp;
            Hst[h_base + (size_t)bb * H_ + j] = hnew;
        }

        if (tau != S_ - 1) grid_barrier();
    }
}

// ---------------------------------------------------------------------------
// Kernel 4: projection  out[b][s][e] = concat(Hf[s*B+b], Hb[s*B+b]) @ Wproj^T
// M=16384, N=512, K=1024 (K<512 from Hf, else Hb). Output written transposed
// to [B][S][E] via strided store (tile rows = consecutive b for fixed s).
// ---------------------------------------------------------------------------
__global__ void proj_gemm_kernel(const float* __restrict__ Wp,
                                 float* __restrict__ out) {
    const int n0 = blockIdx.x * 64;
    const int m0 = blockIdx.y * 128;

    __shared__ __align__(16) float As[128][32];
    __shared__ __align__(16) float Bs[64][40];

    const int tid  = threadIdx.x;
    const int warp = tid >> 5;
    const int wm = (warp & 3) * 32;
    const int wn = (warp >> 2) * 32;

    wmma::fragment<wmma::accumulator, 16, 16, 8, float> acc[2][2];
    #pragma unroll
    for (int i = 0; i < 2; i++)
        #pragma unroll
        for (int j = 0; j < 2; j++)
            wmma::fill_fragment(acc[i][j], 0.0f);

    for (int k0 = 0; k0 < 2 * H_; k0 += 32) {
        const float* __restrict__ Asrc = (k0 < H_) ? g_Hbuf[0] : g_Hbuf[1];
        const int kc = (k0 < H_) ? k0 : (k0 - H_);
        #pragma unroll
        for (int i = 0; i < 4; i++) {            // A: 128x32
            int idx = i * 256 + tid;
            int r = idx >> 3, c = (idx & 7) << 2;
            float4 v = *(const float4*)&Asrc[(size_t)(m0 + r) * H_ + kc + c];
            *(float4*)&As[r][c] = v;
        }
        #pragma unroll
        for (int i = 0; i < 2; i++) {            // B: 64x32 rows of Wproj
            int idx = i * 256 + tid;
            int r = idx >> 3, c = (idx & 7) << 2;
            float4 v = *(const float4*)&Wp[(size_t)(n0 + r) * (2 * H_) + k0 + c];
            *(float4*)&Bs[r][c] = v;
        }
        __syncthreads();

        #pragma unroll
        for (int kk = 0; kk < 32; kk += 8) {
            wmma::fragment<wmma::matrix_a, 16, 16, 8, wmma::precision::tf32, wmma::row_major> a0, a1;
            wmma::fragment<wmma::matrix_b, 16, 16, 8, wmma::precision::tf32, wmma::col_major> b0, b1;
            wmma::load_matrix_sync(a0, &As[wm][kk], 32);
            wmma::load_matrix_sync(a1, &As[wm + 16][kk], 32);
            wmma::load_matrix_sync(b0, &Bs[wn][kk], 40);
            wmma::load_matrix_sync(b1, &Bs[wn + 16][kk], 40);
            #pragma unroll
            for (int i = 0; i < a0.num_elements; i++) {
                a0.x[i] = wmma::__float_to_tf32(a0.x[i]);
                a1.x[i] = wmma::__float_to_tf32(a1.x[i]);
            }
            #pragma unroll
            for (int i = 0; i < b0.num_elements; i++) {
                b0.x[i] = wmma::__float_to_tf32(b0.x[i]);
                b1.x[i] = wmma::__float_to_tf32(b1.x[i]);
            }
            wmma::mma_sync(acc[0][0], a0, b0, acc[0][0]);
            wmma::mma_sync(acc[0][1], a0, b1, acc[0][1]);
            wmma::mma_sync(acc[1][0], a1, b0, acc[1][0]);
            wmma::mma_sync(acc[1][1], a1, b1, acc[1][1]);
        }
        __syncthreads();
    }

    // Output mapping: row m = s*B + b  ->  out[(b*S + s)*E + n]
    const int s    = m0 >> 8;      // m0 / 256
    const int brow = m0 & 255;
    float* __restrict__ Cb = out + ((size_t)brow * S_ + s) * E_;
    const int ldc = S_ * E_;       // consecutive tile rows advance b by 1
    #pragma unroll
    for (int i = 0; i < 2; i++)
        #pragma unroll
        for (int j = 0; j < 2; j++)
            wmma::store_matrix_sync(&Cb[(size_t)(wm + i * 16) * ldc + n0 + wn + j * 16],
                                    acc[i][j], ldc, wmma::mem_row_major);
}

// ---------------------------------------------------------------------------
extern "C" void kernel_launch(void* const* d_in, const int* in_sizes, int n_in,
                              void* d_out, int out_size) {
    const int*   slot_ids = (const int*)d_in[0];
    const float* value    = (const float*)d_in[1];
    const float* table    = (const float*)d_in[2];
    const float* Wih_f    = (const float*)d_in[3];
    const float* Whh_f    = (const float*)d_in[4];
    const float* bih_f    = (const float*)d_in[5];
    const float* bhh_f    = (const float*)d_in[6];
    const float* Wih_b    = (const float*)d_in[7];
    const float* Whh_b    = (const float*)d_in[8];
    const float* bih_b    = (const float*)d_in[9];
    const float* bhh_b    = (const float*)d_in[10];
    const float* Wproj    = (const float*)d_in[11];
    float* out = (float*)d_out;

    cudaFuncSetAttribute(gru_persistent_kernel,
                         cudaFuncAttributeMaxDynamicSharedMemorySize, PSMEM_BYTES);

    build_x_kernel<<<M_, 256>>>(slot_ids, value, table);
    input_gemm_kernel<<<dim3(H3_ / 128, M_ / 128, 2), 256>>>(Wih_f, Wih_b);
    gru_persistent_kernel<<<NCTA, 256, PSMEM_BYTES>>>(
        Whh_f, Whh_b, bih_f, bhh_f, bih_b, bhh_b);
    proj_gemm_kernel<<<dim3(E_ / 64, M_ / 128), 256>>>(Wproj, out);
}

// round 6
// speedup vs baseline: 1.5511x; 1.1791x over previous
#include <cuda_runtime.h>
#include <mma.h>

using namespace nvcuda;

// Problem constants
#define B_    256
#define S_    64
#define DIN_  1024
#define H_    512
#define H3_   1536
#define E_    512
#define M_    (S_ * B_)   // 16384 rows (t*B + b)

#define NCTA  128         // persistent recurrence kernel grid size

// Scratch (device globals; no runtime allocation allowed)
__device__ float g_X[(size_t)M_ * DIN_];         // [t*B+b][1024]  (tf32-rounded)
__device__ float g_Wih[2][(size_t)H3_ * DIN_];   // tf32-rounded weights
__device__ float g_Wproj[(size_t)E_ * 2 * H_];   // tf32-rounded
__device__ float g_GI[2][(size_t)M_ * H3_];      // input-transform, per dir, NO bias
__device__ float g_Hbuf[2][(size_t)M_ * H_];     // fp32 GRU outputs (trajectory)
__device__ float g_Hr[2][(size_t)M_ * H_];       // tf32-rounded GRU outputs (GEMM input)

// Grid barrier state
__device__ volatile unsigned g_bar_count = 0;
__device__ volatile unsigned g_bar_gen   = 0;

__device__ __forceinline__ void grid_barrier() {
    __syncthreads();
    if (threadIdx.x == 0) {
        __threadfence();
        unsigned gen = g_bar_gen;
        unsigned arrived = atomicAdd((unsigned*)&g_bar_count, 1u);
        if (arrived == NCTA - 1) {
            g_bar_count = 0;
            __threadfence();
            atomicAdd((unsigned*)&g_bar_gen, 1u);
        } else {
            while (g_bar_gen == gen) { __nanosleep(32); }
            __threadfence();
        }
    }
    __syncthreads();
}

// cp.async helpers (16B)
__device__ __forceinline__ void cp16(void* s, const void* g) {
    unsigned a = (unsigned)__cvta_generic_to_shared(s);
    asm volatile("cp.async.cg.shared.global [%0], [%1], 16;\n" :: "r"(a), "l"(g));
}
__device__ __forceinline__ void cp_commit() {
    asm volatile("cp.async.commit_group;\n" ::);
}
template <int N> __device__ __forceinline__ void cp_wait() {
    asm volatile("cp.async.wait_group %0;\n" :: "n"(N));
}

__device__ __forceinline__ float4 tf32x4(float4 v) {
    v.x = wmma::__float_to_tf32(v.x); v.y = wmma::__float_to_tf32(v.y);
    v.z = wmma::__float_to_tf32(v.z); v.w = wmma::__float_to_tf32(v.w);
    return v;
}

// ---------------------------------------------------------------------------
// Kernel 0: round weights to tf32 into scratch
// ---------------------------------------------------------------------------
__global__ void round_weights_kernel(const float4* __restrict__ wf,
                                     const float4* __restrict__ wb,
                                     const float4* __restrict__ wp) {
    const int NW = H3_ * DIN_ / 4;   // 393216
    const int NP = E_ * 2 * H_ / 4;  // 131072
    int i = blockIdx.x * blockDim.x + threadIdx.x;
    if (i < NW) {
        ((float4*)g_Wih[0])[i] = tf32x4(wf[i]);
        ((float4*)g_Wih[1])[i] = tf32x4(wb[i]);
        if (i < NP) ((float4*)g_Wproj)[i] = tf32x4(wp[i]);
    }
}

// ---------------------------------------------------------------------------
// Kernel 1: gather slot embedding + concat value embeds -> X (tf32-rounded)
// ---------------------------------------------------------------------------
__global__ void build_x_kernel(const int* __restrict__ slot_ids,
                               const float* __restrict__ value_embeds,
                               const float* __restrict__ embed_table) {
    int m = blockIdx.x;            // = t*B + b
    int t = m >> 8;
    int b = m & 255;
    int c4 = threadIdx.x;          // float4 column 0..255
    float4 v;
    if (c4 < 64) {
        int sid = slot_ids[b * S_ + t];
        v = ((const float4*)embed_table)[(size_t)sid * 64 + c4];
    } else {
        v = ((const float4*)value_embeds)[(size_t)(b * S_ + t) * 192 + (c4 - 64)];
    }
    ((float4*)g_X)[(size_t)m * 256 + c4] = tf32x4(v);
}

// ---------------------------------------------------------------------------
// Kernel 2: input GEMM  GI[dir] = X @ W_ih[dir]^T   (M=16384, N=1536, K=1024)
// 128x128 tile, 8 warps (2Mx4N), warp 64x32, K-step 32, 2-stage cp.async.
// Inputs pre-rounded to tf32 -> no F2F in mainloop.
// ---------------------------------------------------------------------------
#define GSMEM_BYTES (2 * 2 * 128 * 40 * 4)   // 81920

__global__ __launch_bounds__(256, 2)
void input_gemm_kernel() {
    extern __shared__ float sm[];
    float (*As)[128][40] = (float(*)[128][40])sm;
    float (*Bs)[128][40] = (float(*)[128][40])(sm + 2 * 128 * 40);

    const float* __restrict__ A = g_X;
    const float* __restrict__ W = g_Wih[blockIdx.z];
    float* __restrict__ C = g_GI[blockIdx.z];
    const int n0 = blockIdx.x * 128;
    const int m0 = blockIdx.y * 128;

    const int tid  = threadIdx.x;
    const int warp = tid >> 5;
    const int wm = (warp & 1) * 64;
    const int wn = (warp >> 1) * 32;
    const int r8 = tid >> 3, c4 = (tid & 7) << 2;

    wmma::fragment<wmma::accumulator, 16, 16, 8, float> acc[4][2];
    #pragma unroll
    for (int i = 0; i < 4; i++)
        #pragma unroll
        for (int j = 0; j < 2; j++)
            wmma::fill_fragment(acc[i][j], 0.0f);

    auto stage = [&](int s, int kt) {
        const float* Ap = A + (size_t)m0 * DIN_ + kt * 32;
        const float* Wp = W + (size_t)n0 * DIN_ + kt * 32;
        #pragma unroll
        for (int i = 0; i < 4; i++)
            cp16(&As[s][i * 32 + r8][c4], Ap + (size_t)(i * 32 + r8) * DIN_ + c4);
        #pragma unroll
        for (int i = 0; i < 4; i++)
            cp16(&Bs[s][i * 32 + r8][c4], Wp + (size_t)(i * 32 + r8) * DIN_ + c4);
    };

    stage(0, 0); cp_commit();
    for (int kt = 0; kt < 32; kt++) {
        if (kt < 31) { stage((kt + 1) & 1, kt + 1); cp_commit(); cp_wait<1>(); }
        else         { cp_wait<0>(); }
        __syncthreads();
        const int s = kt & 1;
        #pragma unroll
        for (int kk = 0; kk < 32; kk += 8) {
            wmma::fragment<wmma::matrix_a, 16, 16, 8, wmma::precision::tf32, wmma::row_major> a[4];
            wmma::fragment<wmma::matrix_b, 16, 16, 8, wmma::precision::tf32, wmma::col_major> b[2];
            #pragma unroll
            for (int i = 0; i < 4; i++)
                wmma::load_matrix_sync(a[i], &As[s][wm + i * 16][kk], 40);
            #pragma unroll
            for (int j = 0; j < 2; j++)
                wmma::load_matrix_sync(b[j], &Bs[s][wn + j * 16][kk], 40);
            #pragma unroll
            for (int i = 0; i < 4; i++)
                #pragma unroll
                for (int j = 0; j < 2; j++)
                    wmma::mma_sync(acc[i][j], a[i], b[j], acc[i][j]);
        }
        __syncthreads();
    }

    #pragma unroll
    for (int i = 0; i < 4; i++)
        #pragma unroll
        for (int j = 0; j < 2; j++)
            wmma::store_matrix_sync(&C[(size_t)(m0 + wm + i * 16) * H3_ + n0 + wn + j * 16],
                                    acc[i][j], H3_, wmma::mem_row_major);
}

// ---------------------------------------------------------------------------
// Kernel 3: PERSISTENT bidirectional GRU recurrence. 128 CTAs, 64 steps,
// grid barrier between steps. Whh slice resident in SMEM; A staging from
// pre-rounded g_Hr via 2-stage cp.async. Writes fp32 h + tf32-rounded h.
// ---------------------------------------------------------------------------
#define PSMEM_FLOATS (3 * 16 * 520 + 2 * 128 * 40 + 3 * 128 * 16)
#define PSMEM_BYTES  (PSMEM_FLOATS * 4)     // 165376

__global__ __launch_bounds__(256, 1)
void gru_persistent_kernel(const float* __restrict__ Whh_f,
                           const float* __restrict__ Whh_b,
                           const float* __restrict__ bih_f,
                           const float* __restrict__ bhh_f,
                           const float* __restrict__ bih_b,
                           const float* __restrict__ bhh_b) {
    extern __shared__ float sm[];
    float (*Wsm)[16][520]  = (float(*)[16][520])sm;                       // [3][16][520]
    float (*Asm)[128][40]  = (float(*)[128][40])(sm + 3 * 16 * 520);      // [2][128][40]
    float (*GHsm)[128][16] = (float(*)[128][16])(sm + 3 * 16 * 520 + 2 * 128 * 40);

    const int cta = blockIdx.x;
    const int dir = cta >> 6;
    const int rem = cta & 63;
    const int j0  = (rem >> 1) * 16;
    const int b0  = (rem & 1) * 128;

    const int tid  = threadIdx.x;
    const int warp = tid >> 5;
    const int r8 = tid >> 3, c4 = (tid & 7) << 2;

    const float* __restrict__ Whh = dir ? Whh_b : Whh_f;
    const float* __restrict__ bih = dir ? bih_b : bih_f;
    const float* __restrict__ bhh = dir ? bhh_b : bhh_f;
    float* __restrict__ GI  = g_GI[dir];
    float* __restrict__ Hst = g_Hbuf[dir];
    float* __restrict__ Hrd = g_Hr[dir];

    // Per-thread epilogue column is fixed: c = tid & 15  ->  j = j0 + c.
    const int jc = j0 + (tid & 15);
    const float bias_r  = bih[jc]           + bhh[jc];
    const float bias_z  = bih[H_ + jc]      + bhh[H_ + jc];
    const float bias_in = bih[2 * H_ + jc];
    const float bias_hn = bhh[2 * H_ + jc];

    // Load this CTA's Whh slice into SMEM once (tf32-rounded).
    for (int idx = tid; idx < 6144; idx += 256) {
        int row = idx >> 7;           // 0..47
        int cc  = idx & 127;
        int g = row >> 4, jl = row & 15;
        float4 v = *(const float4*)&Whh[((size_t)(g * H_ + j0 + jl)) * H_ + (cc << 2)];
        *(float4*)&Wsm[g][jl][cc << 2] = tf32x4(v);
    }
    __syncthreads();

    for (int tau = 0; tau < S_; tau++) {
        const int row_store = dir ? (S_ - 1 - tau) : tau;
        const float* __restrict__ hprev = nullptr;

        if (tau > 0) {
            const int row_prev = dir ? (S_ - tau) : (tau - 1);
            hprev = &Hst[(size_t)row_prev * B_ * H_];
            const float* __restrict__ hr = &Hrd[(size_t)row_prev * B_ * H_];

            wmma::fragment<wmma::accumulator, 16, 16, 8, float> acc[3];
            #pragma unroll
            for (int g = 0; g < 3; g++) wmma::fill_fragment(acc[g], 0.0f);

            auto stage = [&](int s, int kt) {
                #pragma unroll
                for (int i = 0; i < 4; i++)
                    cp16(&Asm[s][i * 32 + r8][c4],
                         &hr[(size_t)(b0 + i * 32 + r8) * H_ + kt * 32 + c4]);
            };

            stage(0, 0); cp_commit();
            for (int kt = 0; kt < 16; kt++) {
                if (kt < 15) { stage((kt + 1) & 1, kt + 1); cp_commit(); cp_wait<1>(); }
                else         { cp_wait<0>(); }
                __syncthreads();
                const int ss = kt & 1;
                #pragma unroll
                for (int kk = 0; kk < 32; kk += 8) {
                    wmma::fragment<wmma::matrix_a, 16, 16, 8, wmma::precision::tf32, wmma::row_major> a;
                    wmma::load_matrix_sync(a, &Asm[ss][warp * 16][kk], 40);
                    #pragma unroll
                    for (int g = 0; g < 3; g++) {
                        wmma::fragment<wmma::matrix_b, 16, 16, 8, wmma::precision::tf32, wmma::col_major> bf;
                        wmma::load_matrix_sync(bf, &Wsm[g][0][kt * 32 + kk], 520);
                        wmma::mma_sync(acc[g], a, bf, acc[g]);
                    }
                }
                __syncthreads();
            }
            #pragma unroll
            for (int g = 0; g < 3; g++)
                wmma::store_matrix_sync(&GHsm[g][warp * 16][0], acc[g], 16, wmma::mem_row_major);
            __syncthreads();
        }

        // Gate epilogue: 128 rows x 16 j, 8 elems per thread (c fixed per thread)
        const size_t gi_base = (size_t)(row_store * B_) * H3_;
        const size_t h_base  = (size_t)(row_store * B_) * H_;
        const int c = tid & 15;
        #pragma unroll
        for (int k = 0; k < 8; k++) {
            int r = (tid >> 4) + 16 * k;
            int bb = b0 + r;
            float hr = 0.f, hz = 0.f, hn = 0.f, hp = 0.f;
            if (tau > 0) {
                hr = GHsm[0][r][c];
                hz = GHsm[1][r][c];
                hn = GHsm[2][r][c];
                hp = hprev[(size_t)bb * H_ + jc];
            }
            size_t girow = gi_base + (size_t)bb * H3_;
            float ir  = GI[girow + jc];
            float iz  = GI[girow + H_ + jc];
            float inn = GI[girow + 2 * H_ + jc];
            float rg = 1.f / (1.f + expf(-(ir + hr + bias_r)));
            float zg = 1.f / (1.f + expf(-(iz + hz + bias_z)));
            float ng = tanhf(inn + bias_in + rg * (hn + bias_hn));
            float hnew = (1.f - zg) * ng + zg * hp;
            Hst[h_base + (size_t)bb * H_ + jc] = hnew;
            Hrd[h_base + (size_t)bb * H_ + jc] = wmma::__float_to_tf32(hnew);
        }

        if (tau != S_ - 1) grid_barrier();
    }
}

// ---------------------------------------------------------------------------
// Kernel 4: projection  out[b][s][e] = concat(Hf, Hb) @ Wproj^T
// Same pipelined 128x128 template; A from pre-rounded g_Hr (dir switch at
// kt=16). Output written transposed to [B][S][E].
// ---------------------------------------------------------------------------
__global__ __launch_bounds__(256, 2)
void proj_gemm_kernel(float* __restrict__ out) {
    extern __shared__ float sm[];
    float (*As)[128][40] = (float(*)[128][40])sm;
    float (*Bs)[128][40] = (float(*)[128][40])(sm + 2 * 128 * 40);

    const int n0 = blockIdx.x * 128;
    const int m0 = blockIdx.y * 128;

    const int tid  = threadIdx.x;
    const int warp = tid >> 5;
    const int wm = (warp & 1) * 64;
    const int wn = (warp >> 1) * 32;
    const int r8 = tid >> 3, c4 = (tid & 7) << 2;

    wmma::fragment<wmma::accumulator, 16, 16, 8, float> acc[4][2];
    #pragma unroll
    for (int i = 0; i < 4; i++)
        #pragma unroll
        for (int j = 0; j < 2; j++)
            wmma::fill_fragment(acc[i][j], 0.0f);

    auto stage = [&](int s, int kt) {
        const float* Ap = (kt < 16) ? g_Hr[0] : g_Hr[1];
        const int kc = (kt & 15) * 32;
        #pragma unroll
        for (int i = 0; i < 4; i++)
            cp16(&As[s][i * 32 + r8][c4],
                 &Ap[(size_t)(m0 + i * 32 + r8) * H_ + kc + c4]);
        const float* Wp = g_Wproj + (size_t)n0 * (2 * H_) + kt * 32;
        #pragma unroll
        for (int i = 0; i < 4; i++)
            cp16(&Bs[s][i * 32 + r8][c4], Wp + (size_t)(i * 32 + r8) * (2 * H_) + c4);
    };

    stage(0, 0); cp_commit();
    for (int kt = 0; kt < 32; kt++) {
        if (kt < 31) { stage((kt + 1) & 1, kt + 1); cp_commit(); cp_wait<1>(); }
        else         { cp_wait<0>(); }
        __syncthreads();
        const int s = kt & 1;
        #pragma unroll
        for (int kk = 0; kk < 32; kk += 8) {
            wmma::fragment<wmma::matrix_a, 16, 16, 8, wmma::precision::tf32, wmma::row_major> a[4];
            wmma::fragment<wmma::matrix_b, 16, 16, 8, wmma::precision::tf32, wmma::col_major> b[2];
            #pragma unroll
            for (int i = 0; i < 4; i++)
                wmma::load_matrix_sync(a[i], &As[s][wm + i * 16][kk], 40);
            #pragma unroll
            for (int j = 0; j < 2; j++)
                wmma::load_matrix_sync(b[j], &Bs[s][wn + j * 16][kk], 40);
            #pragma unroll
            for (int i = 0; i < 4; i++)
                #pragma unroll
                for (int j = 0; j < 2; j++)
                    wmma::mma_sync(acc[i][j], a[i], b[j], acc[i][j]);
        }
        __syncthreads();
    }

    // Output mapping: row m = s*B + b  ->  out[(b*S + s)*E + n]
    const int sidx = m0 >> 8;
    const int brow = m0 & 255;
    float* __restrict__ Cb = out + ((size_t)brow * S_ + sidx) * E_;
    const int ldc = S_ * E_;
    #pragma unroll
    for (int i = 0; i < 4; i++)
        #pragma unroll
        for (int j = 0; j < 2; j++)
            wmma::store_matrix_sync(&Cb[(size_t)(wm + i * 16) * ldc + n0 + wn + j * 16],
                                    acc[i][j], ldc, wmma::mem_row_major);
}

// ---------------------------------------------------------------------------
extern "C" void kernel_launch(void* const* d_in, const int* in_sizes, int n_in,
                              void* d_out, int out_size) {
    const int*   slot_ids = (const int*)d_in[0];
    const float* value    = (const float*)d_in[1];
    const float* table    = (const float*)d_in[2];
    const float* Wih_f    = (const float*)d_in[3];
    const float* Whh_f    = (const float*)d_in[4];
    const float* bih_f    = (const float*)d_in[5];
    const float* bhh_f    = (const float*)d_in[6];
    const float* Wih_b    = (const float*)d_in[7];
    const float* Whh_b    = (const float*)d_in[8];
    const float* bih_b    = (const float*)d_in[9];
    const float* bhh_b    = (const float*)d_in[10];
    const float* Wproj    = (const float*)d_in[11];
    float* out = (float*)d_out;

    cudaFuncSetAttribute(input_gemm_kernel,
                         cudaFuncAttributeMaxDynamicSharedMemorySize, GSMEM_BYTES);
    cudaFuncSetAttribute(proj_gemm_kernel,
                         cudaFuncAttributeMaxDynamicSharedMemorySize, GSMEM_BYTES);
    cudaFuncSetAttribute(gru_persistent_kernel,
                         cudaFuncAttributeMaxDynamicSharedMemorySize, PSMEM_BYTES);

    round_weights_kernel<<<(H3_ * DIN_ / 4 + 255) / 256, 256>>>(
        (const float4*)Wih_f, (const float4*)Wih_b, (const float4*)Wproj);
    build_x_kernel<<<M_, 256>>>(slot_ids, value, table);
    input_gemm_kernel<<<dim3(H3_ / 128, M_ / 128, 2), 256, GSMEM_BYTES>>>();
    gru_persistent_kernel<<<NCTA, 256, PSMEM_BYTES>>>(
        Whh_f, Whh_b, bih_f, bhh_f, bih_b, bhh_b);
    proj_gemm_kernel<<<dim3(E_ / 128, M_ / 128), 256, GSMEM_BYTES>>>(out);
}

// round 8
// speedup vs baseline: 3.1194x; 2.0111x over previous
#include <cuda_runtime.h>
#include <mma.h>
#include <cstdint>

// Problem constants
#define B_    256
#define S_    64
#define DIN_  1024
#define H_    512
#define H3_   1536
#define E_    512
#define M_    (S_ * B_)   // 16384 rows (t*B + b)

#define NCTA  128         // persistent recurrence kernel grid size

// Scratch (device globals; no runtime allocation allowed)
__device__ float g_X[(size_t)M_ * DIN_];         // [t*B+b][1024]  (tf32-rounded)
__device__ float g_Wih[2][(size_t)H3_ * DIN_];   // tf32-rounded weights
__device__ float g_Wproj[(size_t)E_ * 2 * H_];   // tf32-rounded
__device__ float g_GI[2][(size_t)M_ * H3_];      // input-transform, per dir, NO bias
__device__ float g_Hbuf[2][(size_t)M_ * H_];     // fp32 GRU outputs (trajectory)
__device__ float g_Hr[2][(size_t)M_ * H_];       // tf32-rounded GRU outputs (GEMM input)

// Grid barrier state
__device__ volatile unsigned g_bar_count = 0;
__device__ volatile unsigned g_bar_gen   = 0;

__device__ __forceinline__ void grid_barrier() {
    __syncthreads();
    if (threadIdx.x == 0) {
        __threadfence();
        unsigned gen = g_bar_gen;
        unsigned arrived = atomicAdd((unsigned*)&g_bar_count, 1u);
        if (arrived == NCTA - 1) {
            g_bar_count = 0;
            __threadfence();
            atomicAdd((unsigned*)&g_bar_gen, 1u);
        } else {
            while (g_bar_gen == gen) { __nanosleep(32); }
            __threadfence();
        }
    }
    __syncthreads();
}

// ---------------- low-level helpers ----------------
__device__ __forceinline__ void cp16s(uint32_t s, const void* g) {
    asm volatile("cp.async.cg.shared.global [%0], [%1], 16;\n" :: "r"(s), "l"(g));
}
__device__ __forceinline__ void cp_commit() {
    asm volatile("cp.async.commit_group;\n" ::);
}
template <int N> __device__ __forceinline__ void cp_wait() {
    asm volatile("cp.async.wait_group %0;\n" :: "n"(N));
}

__device__ __forceinline__ float4 tf32x4(float4 v) {
    v.x = nvcuda::wmma::__float_to_tf32(v.x); v.y = nvcuda::wmma::__float_to_tf32(v.y);
    v.z = nvcuda::wmma::__float_to_tf32(v.z); v.w = nvcuda::wmma::__float_to_tf32(v.w);
    return v;
}

__device__ __forceinline__ void ldsm4(uint32_t& r0, uint32_t& r1, uint32_t& r2,
                                      uint32_t& r3, uint32_t addr) {
    asm volatile("ldmatrix.sync.aligned.m8n8.x4.shared.b16 {%0,%1,%2,%3}, [%4];"
                 : "=r"(r0), "=r"(r1), "=r"(r2), "=r"(r3) : "r"(addr));
}

__device__ __forceinline__ void mma8(float* d, const uint32_t* a,
                                     uint32_t b0, uint32_t b1) {
    asm volatile(
        "mma.sync.aligned.m16n8k8.row.col.f32.tf32.tf32.f32 "
        "{%0,%1,%2,%3},{%4,%5,%6,%7},{%8,%9},{%0,%1,%2,%3};"
        : "+f"(d[0]), "+f"(d[1]), "+f"(d[2]), "+f"(d[3])
        : "r"(a[0]), "r"(a[1]), "r"(a[2]), "r"(a[3]), "r"(b0), "r"(b1));
}

// ---------------------------------------------------------------------------
// Kernel 0: round weights to tf32 into scratch
// ---------------------------------------------------------------------------
__global__ void round_weights_kernel(const float4* __restrict__ wf,
                                     const float4* __restrict__ wb,
                                     const float4* __restrict__ wp) {
    const int NW = H3_ * DIN_ / 4;   // 393216
    const int NP = E_ * 2 * H_ / 4;  // 131072
    int i = blockIdx.x * blockDim.x + threadIdx.x;
    if (i < NW) {
        ((float4*)g_Wih[0])[i] = tf32x4(wf[i]);
        ((float4*)g_Wih[1])[i] = tf32x4(wb[i]);
        if (i < NP) ((float4*)g_Wproj)[i] = tf32x4(wp[i]);
    }
}

// ---------------------------------------------------------------------------
// Kernel 1: gather slot embedding + concat value embeds -> X (tf32-rounded)
// ---------------------------------------------------------------------------
__global__ void build_x_kernel(const int* __restrict__ slot_ids,
                               const float* __restrict__ value_embeds,
                               const float* __restrict__ embed_table) {
    int m = blockIdx.x;            // = t*B + b
    int t = m >> 8;
    int b = m & 255;
    int c4 = threadIdx.x;          // float4 column 0..255
    float4 v;
    if (c4 < 64) {
        int sid = slot_ids[b * S_ + t];
        v = ((const float4*)embed_table)[(size_t)sid * 64 + c4];
    } else {
        v = ((const float4*)value_embeds)[(size_t)(b * S_ + t) * 192 + (c4 - 64)];
    }
    ((float4*)g_X)[(size_t)m * 256 + c4] = tf32x4(v);
}

// ---------------------------------------------------------------------------
// Kernel 2/4: raw mma.sync tf32 GEMM.
//   PROJ=false: GI[dir] = X @ Wih[dir]^T   (M=16384, N=1536, K=1024)
//   PROJ=true:  out = concat(Hf,Hb) @ Wproj^T, stored transposed to [B][S][E]
// CTA 128x256, 8 warps (2Mx4N), warp 64x64. K staged in 32-float (128B) SW128
// rows, 2-stage cp.async double buffer, conflict-free ldmatrix.
// SMEM: A[2][128][32] @0 (32KB), B[2][256][32] @32KB (64KB). Total 96KB.
// ---------------------------------------------------------------------------
#define GSMEM_BYTES 98304

template <bool PROJ>
__global__ __launch_bounds__(256, 1)
void mm_gemm_kernel(float* __restrict__ outp) {
    extern __shared__ __align__(128) float smem[];
    const uint32_t sbase = (uint32_t)__cvta_generic_to_shared(smem);
    const int tid  = threadIdx.x;
    const int lane = tid & 31;
    const int warp = tid >> 5;
    const int n0  = blockIdx.x * 256;
    const int m0  = blockIdx.y * 128;
    const int dir = blockIdx.z;

    const float* __restrict__ Wg = PROJ ? g_Wproj : g_Wih[dir];

    const int wm = (warp & 1) * 64;
    const int wn = (warp >> 1) * 64;

    // ldmatrix per-thread row/chunk selectors (see fragment mapping derivation)
    const int a_rr = lane & 15;
    const int a_cs = lane >> 4;
    const int b_rr = (lane & 7) | ((lane & 16) >> 1);
    const int b_cs = (lane >> 3) & 1;

    float acc[4][8][4];
    #pragma unroll
    for (int i = 0; i < 4; i++)
        #pragma unroll
        for (int j = 0; j < 8; j++)
            #pragma unroll
            for (int e = 0; e < 4; e++) acc[i][j][e] = 0.0f;

    auto stage = [&](int s, int kt) {
        // A: 128 rows x 8 chunks = 1024 cp16
        #pragma unroll
        for (int q = 0; q < 4; q++) {
            int id = tid + q * 256;
            int r = id >> 3, c8 = id & 7;
            const float* src;
            if (PROJ) {
                const float* hs = (kt < 16) ? g_Hr[0] : g_Hr[1];
                src = &hs[(size_t)(m0 + r) * H_ + (kt & 15) * 32 + c8 * 4];
            } else {
                src = &g_X[(size_t)(m0 + r) * DIN_ + kt * 32 + c8 * 4];
            }
            cp16s(sbase + s * 16384 + r * 128 + ((c8 ^ (r & 7)) << 4), src);
        }
        // B: 256 rows x 8 chunks = 2048 cp16
        #pragma unroll
        for (int q = 0; q < 8; q++) {
            int id = tid + q * 256;
            int r = id >> 3, c8 = id & 7;
            cp16s(sbase + 32768 + s * 32768 + r * 128 + ((c8 ^ (r & 7)) << 4),
                  &Wg[(size_t)(n0 + r) * 1024 + kt * 32 + c8 * 4]);
        }
    };

    stage(0, 0); cp_commit();
    stage(1, 1); cp_commit();

    for (int kt = 0; kt < 32; kt++) {
        const int s = kt & 1;
        if (kt < 31) cp_wait<1>(); else cp_wait<0>();
        __syncthreads();
        const uint32_t sa = sbase + s * 16384;
        const uint32_t sb = sbase + 32768 + s * 32768;

        #pragma unroll
        for (int k8 = 0; k8 < 4; k8++) {
            uint32_t a[4][4];
            #pragma unroll
            for (int mi = 0; mi < 4; mi++) {
                int rr = wm + 16 * mi + a_rr;
                ldsm4(a[mi][0], a[mi][1], a[mi][2], a[mi][3],
                      sa + rr * 128 + (((2 * k8 + a_cs) ^ (rr & 7)) << 4));
            }
            #pragma unroll
            for (int g2 = 0; g2 < 4; g2++) {
                int rr = wn + 16 * g2 + b_rr;
                uint32_t b0, b1, b2, b3;
                ldsm4(b0, b1, b2, b3,
                      sb + rr * 128 + (((2 * k8 + b_cs) ^ (rr & 7)) << 4));
                #pragma unroll
                for (int mi = 0; mi < 4; mi++) {
                    mma8(acc[mi][2 * g2], a[mi], b0, b1);
                    mma8(acc[mi][2 * g2 + 1], a[mi], b2, b3);
                }
            }
        }
        __syncthreads();
        if (kt + 2 < 32) { stage(s, kt + 2); cp_commit(); }
    }

    // Epilogue: d0: (r=lane>>2, c=2*(lane&3)); d1 c+1; d2/d3 row+8
    const int re = lane >> 2, ce = 2 * (lane & 3);
    #pragma unroll
    for (int mi = 0; mi < 4; mi++) {
        #pragma unroll
        for (int j = 0; j < 8; j++) {
            int row = m0 + wm + 16 * mi + re;
            int col = n0 + wn + 8 * j + ce;
            if (!PROJ) {
                float* C = g_GI[dir];
                *(float2*)&C[(size_t)row * H3_ + col] =
                    make_float2(acc[mi][j][0], acc[mi][j][1]);
                *(float2*)&C[(size_t)(row + 8) * H3_ + col] =
                    make_float2(acc[mi][j][2], acc[mi][j][3]);
            } else {
                int r1 = row, r2 = row + 8;
                size_t o1 = ((size_t)(r1 & 255) * S_ + (r1 >> 8)) * E_ + col;
                size_t o2 = ((size_t)(r2 & 255) * S_ + (r2 >> 8)) * E_ + col;
                *(float2*)&outp[o1] = make_float2(acc[mi][j][0], acc[mi][j][1]);
                *(float2*)&outp[o2] = make_float2(acc[mi][j][2], acc[mi][j][3]);
            }
        }
    }
}

// ---------------------------------------------------------------------------
// Kernel 3: PERSISTENT bidirectional GRU recurrence, raw mma.sync version.
// 128 CTAs: dir(2) x j-slice 16(32) x batch-half 128(2).
// Whh slice in SMEM as k-chunked SW128 tiles (conflict-free ldmatrix).
// Warps: 4 M-slices (32 rows) x 2 K-halves (256). Partials summed via SMEM.
// SMEM floats: WSM[16kc][48r][32] = 24576 | ASM[2s][2kh][128r][32] = 16384
//            | GH[2kh][128][48] = 12288.  Total 53248 floats = 208KB.
// ---------------------------------------------------------------------------
#define R_WSM 0
#define R_ASM 24576
#define R_GH  40960
#define PSMEM_BYTES (53248 * 4)

__global__ __launch_bounds__(256, 1)
void gru_persistent_kernel(const float* __restrict__ Whh_f,
                           const float* __restrict__ Whh_b,
                           const float* __restrict__ bih_f,
                           const float* __restrict__ bhh_f,
                           const float* __restrict__ bih_b,
                           const float* __restrict__ bhh_b) {
    extern __shared__ __align__(128) float sm[];
    const uint32_t sbase = (uint32_t)__cvta_generic_to_shared(sm);

    const int cta = blockIdx.x;
    const int dir = cta >> 6;
    const int rem = cta & 63;
    const int j0  = (rem >> 1) * 16;
    const int b0  = (rem & 1) * 128;

    const int tid  = threadIdx.x;
    const int lane = tid & 31;
    const int warp = tid >> 5;
    const int kh   = warp >> 2;        // K-half 0/1
    const int m0w  = (warp & 3) * 32;  // 32-row M slice

    const int a_rr = lane & 15;
    const int a_cs = lane >> 4;
    const int b_rr = (lane & 7) | ((lane & 16) >> 1);
    const int b_cs = (lane >> 3) & 1;

    const float* __restrict__ Whh = dir ? Whh_b : Whh_f;
    const float* __restrict__ bih = dir ? bih_b : bih_f;
    const float* __restrict__ bhh = dir ? bhh_b : bhh_f;
    float* __restrict__ GI  = g_GI[dir];
    float* __restrict__ Hst = g_Hbuf[dir];
    float* __restrict__ Hrd = g_Hr[dir];

    const int jc = j0 + (tid & 15);
    const float bias_r  = bih[jc]           + bhh[jc];
    const float bias_z  = bih[H_ + jc]      + bhh[H_ + jc];
    const float bias_in = bih[2 * H_ + jc];
    const float bias_hn = bhh[2 * H_ + jc];

    // Load Whh slice: rows = gate*16+jl (48), k-chunked SW128 layout, tf32.
    for (int idx = tid; idx < 6144; idx += 256) {
        int row = idx >> 7;          // 0..47
        int f4c = idx & 127;
        int kc = f4c >> 3, c8 = f4c & 7;
        int g = row >> 4, jl = row & 15;
        float4 v = tf32x4(*(const float4*)
            &Whh[((size_t)(g * H_ + j0 + jl)) * H_ + kc * 32 + c8 * 4]);
        *(float4*)&sm[R_WSM + (kc * 48 + row) * 32 + ((c8 ^ (row & 7)) << 2)] = v;
    }
    __syncthreads();

    for (int tau = 0; tau < S_; tau++) {
        const int row_store = dir ? (S_ - 1 - tau) : tau;
        const float* __restrict__ hprev = nullptr;

        if (tau > 0) {
            const int row_prev = dir ? (S_ - tau) : (tau - 1);
            hprev = &Hst[(size_t)row_prev * B_ * H_];
            const float* __restrict__ hr = &Hrd[(size_t)row_prev * B_ * H_];

            float acc[2][6][4];
            #pragma unroll
            for (int i = 0; i < 2; i++)
                #pragma unroll
                for (int j = 0; j < 6; j++)
                    #pragma unroll
                    for (int e = 0; e < 4; e++) acc[i][j][e] = 0.0f;

            auto stage = [&](int s, int i) {
                #pragma unroll
                for (int q = 0; q < 8; q++) {
                    int id = tid + q * 256;       // 0..2047
                    int khs = id >> 10;           // 0/1
                    int r = (id >> 3) & 127, c8 = id & 7;
                    int kc = khs * 8 + i;
                    cp16s(sbase + 4 * (R_ASM + ((s * 2 + khs) * 128 + r) * 32)
                              + ((c8 ^ (r & 7)) << 4),
                          &hr[(size_t)(b0 + r) * H_ + kc * 32 + c8 * 4]);
                }
            };

            stage(0, 0); cp_commit();
            stage(1, 1); cp_commit();

            for (int i = 0; i < 8; i++) {
                const int s = i & 1;
                if (i < 7) cp_wait<1>(); else cp_wait<0>();
                __syncthreads();
                const uint32_t sa = sbase + 4 * (R_ASM + (s * 2 + kh) * 128 * 32);
                const int kc = kh * 8 + i;
                const uint32_t wb = sbase + 4 * (R_WSM + kc * 48 * 32);

                #pragma unroll
                for (int k8 = 0; k8 < 4; k8++) {
                    uint32_t a[2][4];
                    #pragma unroll
                    for (int mi = 0; mi < 2; mi++) {
                        int rr = m0w + 16 * mi + a_rr;
                        ldsm4(a[mi][0], a[mi][1], a[mi][2], a[mi][3],
                              sa + rr * 128 + (((2 * k8 + a_cs) ^ (rr & 7)) << 4));
                    }
                    #pragma unroll
                    for (int g2 = 0; g2 < 3; g2++) {
                        int rr = 16 * g2 + b_rr;
                        uint32_t bb0, bb1, bb2, bb3;
                        ldsm4(bb0, bb1, bb2, bb3,
                              wb + rr * 128 + (((2 * k8 + b_cs) ^ (rr & 7)) << 4));
                        #pragma unroll
                        for (int mi = 0; mi < 2; mi++) {
                            mma8(acc[mi][2 * g2], a[mi], bb0, bb1);
                            mma8(acc[mi][2 * g2 + 1], a[mi], bb2, bb3);
                        }
                    }
                }
                __syncthreads();
                if (i + 2 < 8) { stage(s, i + 2); cp_commit(); }
            }

            // Write partials to GH[kh]
            const int re = lane >> 2, ce = 2 * (lane & 3);
            #pragma unroll
            for (int mi = 0; mi < 2; mi++) {
                #pragma unroll
                for (int j = 0; j < 6; j++) {
                    int row = m0w + 16 * mi + re;
                    int col = 8 * j + ce;
                    int off = R_GH + kh * 6144 + row * 48 + col;
                    *(float2*)&sm[off] = make_float2(acc[mi][j][0], acc[mi][j][1]);
                    *(float2*)&sm[off + 8 * 48] = make_float2(acc[mi][j][2], acc[mi][j][3]);
                }
            }
            __syncthreads();
        }

        // Gate epilogue: 128 rows x 16 j, 8 per thread (fixed col per thread)
        const size_t gi_base = (size_t)(row_store * B_) * H3_;
        const size_t h_base  = (size_t)(row_store * B_) * H_;
        const int c = tid & 15;
        #pragma unroll
        for (int k = 0; k < 8; k++) {
            int r = (tid >> 4) + 16 * k;
            int bb = b0 + r;
            float hr_ = 0.f, hz = 0.f, hn = 0.f, hp = 0.f;
            if (tau > 0) {
                int base = R_GH + r * 48;
                hr_ = sm[base + c]      + sm[base + 6144 + c];
                hz  = sm[base + 16 + c] + sm[base + 6144 + 16 + c];
                hn  = sm[base + 32 + c] + sm[base + 6144 + 32 + c];
                hp  = hprev[(size_t)bb * H_ + jc];
            }
            size_t girow = gi_base + (size_t)bb * H3_;
            float ir  = GI[girow + jc];
            float iz  = GI[girow + H_ + jc];
            float inn = GI[girow + 2 * H_ + jc];
            float rg = 1.f / (1.f + expf(-(ir + hr_ + bias_r)));
            float zg = 1.f / (1.f + expf(-(iz + hz + bias_z)));
            float ng = tanhf(inn + bias_in + rg * (hn + bias_hn));
            float hnew = (1.f - zg) * ng + zg * hp;
            Hst[h_base + (size_t)bb * H_ + jc] = hnew;
            Hrd[h_base + (size_t)bb * H_ + jc] = nvcuda::wmma::__float_to_tf32(hnew);
        }

        if (tau != S_ - 1) grid_barrier();
    }
}

// ---------------------------------------------------------------------------
extern "C" void kernel_launch(void* const* d_in, const int* in_sizes, int n_in,
                              void* d_out, int out_size) {
    const int*   slot_ids = (const int*)d_in[0];
    const float* value    = (const float*)d_in[1];
    const float* table    = (const float*)d_in[2];
    const float* Wih_f    = (const float*)d_in[3];
    const float* Whh_f    = (const float*)d_in[4];
    const float* bih_f    = (const float*)d_in[5];
    const float* bhh_f    = (const float*)d_in[6];
    const float* Wih_b    = (const float*)d_in[7];
    const float* Whh_b    = (const float*)d_in[8];
    const float* bih_b    = (const float*)d_in[9];
    const float* bhh_b    = (const float*)d_in[10];
    const float* Wproj    = (const float*)d_in[11];
    float* out = (float*)d_out;

    cudaFuncSetAttribute(mm_gemm_kernel<false>,
                         cudaFuncAttributeMaxDynamicSharedMemorySize, GSMEM_BYTES);
    cudaFuncSetAttribute(mm_gemm_kernel<true>,
                         cudaFuncAttributeMaxDynamicSharedMemorySize, GSMEM_BYTES);
    cudaFuncSetAttribute(gru_persistent_kernel,
                         cudaFuncAttributeMaxDynamicSharedMemorySize, PSMEM_BYTES);

    round_weights_kernel<<<(H3_ * DIN_ / 4 + 255) / 256, 256>>>(
        (const float4*)Wih_f, (const float4*)Wih_b, (const float4*)Wproj);
    build_x_kernel<<<M_, 256>>>(slot_ids, value, table);
    mm_gemm_kernel<false><<<dim3(H3_ / 256, M_ / 128, 2), 256, GSMEM_BYTES>>>(nullptr);
    gru_persistent_kernel<<<NCTA, 256, PSMEM_BYTES>>>(
        Whh_f, Whh_b, bih_f, bhh_f, bih_b, bhh_b);
    mm_gemm_kernel<true><<<dim3(E_ / 256, M_ / 128, 1), 256, GSMEM_BYTES>>>(out);
}

// round 9
// speedup vs baseline: 3.2060x; 1.0278x over previous
#include <cuda_runtime.h>
#include <mma.h>
#include <cstdint>

// Problem constants
#define B_    256
#define S_    64
#define DIN_  1024
#define H_    512
#define H3_   1536
#define E_    512
#define M_    (S_ * B_)   // 16384 rows (t*B + b)

#define NCTA  128         // persistent recurrence kernel grid size

// Scratch (device globals; no runtime allocation allowed)
__device__ float g_X[(size_t)M_ * DIN_];         // [t*B+b][1024]  (tf32-rounded)
__device__ float g_Wih[2][(size_t)H3_ * DIN_];   // tf32-rounded weights
__device__ float g_Wproj[(size_t)E_ * 2 * H_];   // tf32-rounded
__device__ float g_GI[2][(size_t)M_ * H3_];      // input-transform, per dir, NO bias
__device__ float g_Hbuf[2][(size_t)M_ * H_];     // fp32 GRU outputs (trajectory)
__device__ float g_Hr[2][(size_t)M_ * H_];       // tf32-rounded GRU outputs (GEMM input)

// Grid barrier state
__device__ volatile unsigned g_bar_count = 0;
__device__ volatile unsigned g_bar_gen   = 0;

__device__ __forceinline__ void grid_barrier() {
    __syncthreads();
    if (threadIdx.x == 0) {
        __threadfence();
        unsigned gen = g_bar_gen;
        unsigned arrived = atomicAdd((unsigned*)&g_bar_count, 1u);
        if (arrived == NCTA - 1) {
            g_bar_count = 0;
            __threadfence();
            atomicAdd((unsigned*)&g_bar_gen, 1u);
        } else {
            while (g_bar_gen == gen) { __nanosleep(32); }
            __threadfence();
        }
    }
    __syncthreads();
}

// ---------------- low-level helpers ----------------
__device__ __forceinline__ void cp16s(uint32_t s, const void* g) {
    asm volatile("cp.async.cg.shared.global [%0], [%1], 16;\n" :: "r"(s), "l"(g));
}
__device__ __forceinline__ void cp_commit() {
    asm volatile("cp.async.commit_group;\n" ::);
}
template <int N> __device__ __forceinline__ void cp_wait() {
    asm volatile("cp.async.wait_group %0;\n" :: "n"(N));
}

__device__ __forceinline__ float4 tf32x4(float4 v) {
    v.x = nvcuda::wmma::__float_to_tf32(v.x); v.y = nvcuda::wmma::__float_to_tf32(v.y);
    v.z = nvcuda::wmma::__float_to_tf32(v.z); v.w = nvcuda::wmma::__float_to_tf32(v.w);
    return v;
}

__device__ __forceinline__ float tanhax(float x) {
    float y;
    asm("tanh.approx.f32 %0, %1;" : "=f"(y) : "f"(x));
    return y;
}

__device__ __forceinline__ void ldsm4(uint32_t& r0, uint32_t& r1, uint32_t& r2,
                                      uint32_t& r3, uint32_t addr) {
    asm volatile("ldmatrix.sync.aligned.m8n8.x4.shared.b16 {%0,%1,%2,%3}, [%4];"
                 : "=r"(r0), "=r"(r1), "=r"(r2), "=r"(r3) : "r"(addr));
}

__device__ __forceinline__ void mma8(float* d, const uint32_t* a,
                                     uint32_t b0, uint32_t b1) {
    asm volatile(
        "mma.sync.aligned.m16n8k8.row.col.f32.tf32.tf32.f32 "
        "{%0,%1,%2,%3},{%4,%5,%6,%7},{%8,%9},{%0,%1,%2,%3};"
        : "+f"(d[0]), "+f"(d[1]), "+f"(d[2]), "+f"(d[3])
        : "r"(a[0]), "r"(a[1]), "r"(a[2]), "r"(a[3]), "r"(b0), "r"(b1));
}

// ---------------------------------------------------------------------------
// Kernel 0: round weights to tf32 into scratch
// ---------------------------------------------------------------------------
__global__ void round_weights_kernel(const float4* __restrict__ wf,
                                     const float4* __restrict__ wb,
                                     const float4* __restrict__ wp) {
    const int NW = H3_ * DIN_ / 4;   // 393216
    const int NP = E_ * 2 * H_ / 4;  // 131072
    int i = blockIdx.x * blockDim.x + threadIdx.x;
    if (i < NW) {
        ((float4*)g_Wih[0])[i] = tf32x4(wf[i]);
        ((float4*)g_Wih[1])[i] = tf32x4(wb[i]);
        if (i < NP) ((float4*)g_Wproj)[i] = tf32x4(wp[i]);
    }
}

// ---------------------------------------------------------------------------
// Kernel 1: gather slot embedding + concat value embeds -> X (tf32-rounded)
// ---------------------------------------------------------------------------
__global__ void build_x_kernel(const int* __restrict__ slot_ids,
                               const float* __restrict__ value_embeds,
                               const float* __restrict__ embed_table) {
    int m = blockIdx.x;            // = t*B + b
    int t = m >> 8;
    int b = m & 255;
    int c4 = threadIdx.x;          // float4 column 0..255
    float4 v;
    if (c4 < 64) {
        int sid = slot_ids[b * S_ + t];
        v = ((const float4*)embed_table)[(size_t)sid * 64 + c4];
    } else {
        v = ((const float4*)value_embeds)[(size_t)(b * S_ + t) * 192 + (c4 - 64)];
    }
    ((float4*)g_X)[(size_t)m * 256 + c4] = tf32x4(v);
}

// ---------------------------------------------------------------------------
// Kernel 2/4: raw mma.sync tf32 GEMM, 3-stage cp.async, one sync per K-step.
//   PROJ=false: GI[dir] = X @ Wih[dir]^T   (M=16384, N=1536, K=1024)
//   PROJ=true:  out = concat(Hf,Hb) @ Wproj^T, stored transposed to [B][S][E]
// CTA 128x256, 8 warps (2Mx4N), warp 64x64, SW128-swizzled conflict-free ldsm.
// SMEM: A[3][128][32] @0 (48KB), B[3][256][32] @48KB (96KB). Total 144KB.
// ---------------------------------------------------------------------------
#define GSMEM_BYTES 147456

template <bool PROJ>
__global__ __launch_bounds__(256, 1)
void mm_gemm_kernel(float* __restrict__ outp) {
    extern __shared__ __align__(128) float smem[];
    const uint32_t sbase = (uint32_t)__cvta_generic_to_shared(smem);
    const int tid  = threadIdx.x;
    const int lane = tid & 31;
    const int warp = tid >> 5;
    const int n0  = blockIdx.x * 256;
    const int m0  = blockIdx.y * 128;
    const int dir = blockIdx.z;

    const float* __restrict__ Wg = PROJ ? g_Wproj : g_Wih[dir];

    const int wm = (warp & 1) * 64;
    const int wn = (warp >> 1) * 64;

    const int a_rr = lane & 15;
    const int a_cs = lane >> 4;
    const int b_rr = (lane & 7) | ((lane & 16) >> 1);
    const int b_cs = (lane >> 3) & 1;

    float acc[4][8][4];
    #pragma unroll
    for (int i = 0; i < 4; i++)
        #pragma unroll
        for (int j = 0; j < 8; j++)
            #pragma unroll
            for (int e = 0; e < 4; e++) acc[i][j][e] = 0.0f;

    auto stage = [&](int s, int kt) {
        #pragma unroll
        for (int q = 0; q < 4; q++) {
            int id = tid + q * 256;
            int r = id >> 3, c8 = id & 7;
            const float* src;
            if (PROJ) {
                const float* hs = (kt < 16) ? g_Hr[0] : g_Hr[1];
                src = &hs[(size_t)(m0 + r) * H_ + (kt & 15) * 32 + c8 * 4];
            } else {
                src = &g_X[(size_t)(m0 + r) * DIN_ + kt * 32 + c8 * 4];
            }
            cp16s(sbase + s * 16384 + r * 128 + ((c8 ^ (r & 7)) << 4), src);
        }
        #pragma unroll
        for (int q = 0; q < 8; q++) {
            int id = tid + q * 256;
            int r = id >> 3, c8 = id & 7;
            cp16s(sbase + 49152 + s * 32768 + r * 128 + ((c8 ^ (r & 7)) << 4),
                  &Wg[(size_t)(n0 + r) * 1024 + kt * 32 + c8 * 4]);
        }
    };

    stage(0, 0); cp_commit();
    stage(1, 1); cp_commit();

    for (int kt = 0; kt < 32; kt++) {
        if (kt < 31) cp_wait<1>(); else cp_wait<0>();
        __syncthreads();
        if (kt + 2 < 32) { stage((kt + 2) % 3, kt + 2); cp_commit(); }

        const int s = kt % 3;
        const uint32_t sa = sbase + s * 16384;
        const uint32_t sb = sbase + 49152 + s * 32768;

        #pragma unroll
        for (int k8 = 0; k8 < 4; k8++) {
            uint32_t a[4][4];
            #pragma unroll
            for (int mi = 0; mi < 4; mi++) {
                int rr = wm + 16 * mi + a_rr;
                ldsm4(a[mi][0], a[mi][1], a[mi][2], a[mi][3],
                      sa + rr * 128 + (((2 * k8 + a_cs) ^ (rr & 7)) << 4));
            }
            #pragma unroll
            for (int g2 = 0; g2 < 4; g2++) {
                int rr = wn + 16 * g2 + b_rr;
                uint32_t b0, b1, b2, b3;
                ldsm4(b0, b1, b2, b3,
                      sb + rr * 128 + (((2 * k8 + b_cs) ^ (rr & 7)) << 4));
                #pragma unroll
                for (int mi = 0; mi < 4; mi++) {
                    mma8(acc[mi][2 * g2], a[mi], b0, b1);
                    mma8(acc[mi][2 * g2 + 1], a[mi], b2, b3);
                }
            }
        }
    }

    const int re = lane >> 2, ce = 2 * (lane & 3);
    #pragma unroll
    for (int mi = 0; mi < 4; mi++) {
        #pragma unroll
        for (int j = 0; j < 8; j++) {
            int row = m0 + wm + 16 * mi + re;
            int col = n0 + wn + 8 * j + ce;
            if (!PROJ) {
                float* C = g_GI[dir];
                *(float2*)&C[(size_t)row * H3_ + col] =
                    make_float2(acc[mi][j][0], acc[mi][j][1]);
                *(float2*)&C[(size_t)(row + 8) * H3_ + col] =
                    make_float2(acc[mi][j][2], acc[mi][j][3]);
            } else {
                int r1 = row, r2 = row + 8;
                size_t o1 = ((size_t)(r1 & 255) * S_ + (r1 >> 8)) * E_ + col;
                size_t o2 = ((size_t)(r2 & 255) * S_ + (r2 >> 8)) * E_ + col;
                *(float2*)&outp[o1] = make_float2(acc[mi][j][0], acc[mi][j][1]);
                *(float2*)&outp[o2] = make_float2(acc[mi][j][2], acc[mi][j][3]);
            }
        }
    }
}

// ---------------------------------------------------------------------------
// Kernel 3: PERSISTENT bidirectional GRU recurrence, raw mma.sync version.
// Gate nonlinearities via MUFU.TANH (tanh.approx): sigma(x)=0.5+0.5*tanh(x/2).
// ---------------------------------------------------------------------------
#define R_WSM 0
#define R_ASM 24576
#define R_GH  40960
#define PSMEM_BYTES (53248 * 4)

__global__ __launch_bounds__(256, 1)
void gru_persistent_kernel(const float* __restrict__ Whh_f,
                           const float* __restrict__ Whh_b,
                           const float* __restrict__ bih_f,
                           const float* __restrict__ bhh_f,
                           const float* __restrict__ bih_b,
                           const float* __restrict__ bhh_b) {
    extern __shared__ __align__(128) float sm[];
    const uint32_t sbase = (uint32_t)__cvta_generic_to_shared(sm);

    const int cta = blockIdx.x;
    const int dir = cta >> 6;
    const int rem = cta & 63;
    const int j0  = (rem >> 1) * 16;
    const int b0  = (rem & 1) * 128;

    const int tid  = threadIdx.x;
    const int lane = tid & 31;
    const int warp = tid >> 5;
    const int kh   = warp >> 2;        // K-half 0/1
    const int m0w  = (warp & 3) * 32;  // 32-row M slice

    const int a_rr = lane & 15;
    const int a_cs = lane >> 4;
    const int b_rr = (lane & 7) | ((lane & 16) >> 1);
    const int b_cs = (lane >> 3) & 1;

    const float* __restrict__ Whh = dir ? Whh_b : Whh_f;
    const float* __restrict__ bih = dir ? bih_b : bih_f;
    const float* __restrict__ bhh = dir ? bhh_b : bhh_f;
    float* __restrict__ GI  = g_GI[dir];
    float* __restrict__ Hst = g_Hbuf[dir];
    float* __restrict__ Hrd = g_Hr[dir];

    const int jc = j0 + (tid & 15);
    const float bias_r  = bih[jc]           + bhh[jc];
    const float bias_z  = bih[H_ + jc]      + bhh[H_ + jc];
    const float bias_in = bih[2 * H_ + jc];
    const float bias_hn = bhh[2 * H_ + jc];

    // Load Whh slice: rows = gate*16+jl (48), k-chunked SW128 layout, tf32.
    for (int idx = tid; idx < 6144; idx += 256) {
        int row = idx >> 7;          // 0..47
        int f4c = idx & 127;
        int kc = f4c >> 3, c8 = f4c & 7;
        int g = row >> 4, jl = row & 15;
        float4 v = tf32x4(*(const float4*)
            &Whh[((size_t)(g * H_ + j0 + jl)) * H_ + kc * 32 + c8 * 4]);
        *(float4*)&sm[R_WSM + (kc * 48 + row) * 32 + ((c8 ^ (row & 7)) << 2)] = v;
    }
    __syncthreads();

    for (int tau = 0; tau < S_; tau++) {
        const int row_store = dir ? (S_ - 1 - tau) : tau;
        const float* __restrict__ hprev = nullptr;

        if (tau > 0) {
            const int row_prev = dir ? (S_ - tau) : (tau - 1);
            hprev = &Hst[(size_t)row_prev * B_ * H_];
            const float* __restrict__ hr = &Hrd[(size_t)row_prev * B_ * H_];

            float acc[2][6][4];
            #pragma unroll
            for (int i = 0; i < 2; i++)
                #pragma unroll
                for (int j = 0; j < 6; j++)
                    #pragma unroll
                    for (int e = 0; e < 4; e++) acc[i][j][e] = 0.0f;

            auto stage = [&](int s, int i) {
                #pragma unroll
                for (int q = 0; q < 8; q++) {
                    int id = tid + q * 256;       // 0..2047
                    int khs = id >> 10;           // 0/1
                    int r = (id >> 3) & 127, c8 = id & 7;
                    int kc = khs * 8 + i;
                    cp16s(sbase + 4 * (R_ASM + ((s * 2 + khs) * 128 + r) * 32)
                              + ((c8 ^ (r & 7)) << 4),
                          &hr[(size_t)(b0 + r) * H_ + kc * 32 + c8 * 4]);
                }
            };

            stage(0, 0); cp_commit();
            stage(1, 1); cp_commit();

            for (int i = 0; i < 8; i++) {
                const int s = i & 1;
                if (i < 7) cp_wait<1>(); else cp_wait<0>();
                __syncthreads();
                const uint32_t sa = sbase + 4 * (R_ASM + (s * 2 + kh) * 128 * 32);
                const int kc = kh * 8 + i;
                const uint32_t wb = sbase + 4 * (R_WSM + kc * 48 * 32);

                #pragma unroll
                for (int k8 = 0; k8 < 4; k8++) {
                    uint32_t a[2][4];
                    #pragma unroll
                    for (int mi = 0; mi < 2; mi++) {
                        int rr = m0w + 16 * mi + a_rr;
                        ldsm4(a[mi][0], a[mi][1], a[mi][2], a[mi][3],
                              sa + rr * 128 + (((2 * k8 + a_cs) ^ (rr & 7)) << 4));
                    }
                    #pragma unroll
                    for (int g2 = 0; g2 < 3; g2++) {
                        int rr = 16 * g2 + b_rr;
                        uint32_t bb0, bb1, bb2, bb3;
                        ldsm4(bb0, bb1, bb2, bb3,
                              wb + rr * 128 + (((2 * k8 + b_cs) ^ (rr & 7)) << 4));
                        #pragma unroll
                        for (int mi = 0; mi < 2; mi++) {
                            mma8(acc[mi][2 * g2], a[mi], bb0, bb1);
                            mma8(acc[mi][2 * g2 + 1], a[mi], bb2, bb3);
                        }
                    }
                }
                __syncthreads();
                if (i + 2 < 8) { stage(s, i + 2); cp_commit(); }
            }

            // Write partials to GH[kh]
            const int re = lane >> 2, ce = 2 * (lane & 3);
            #pragma unroll
            for (int mi = 0; mi < 2; mi++) {
                #pragma unroll
                for (int j = 0; j < 6; j++) {
                    int row = m0w + 16 * mi + re;
                    int col = 8 * j + ce;
                    int off = R_GH + kh * 6144 + row * 48 + col;
                    *(float2*)&sm[off] = make_float2(acc[mi][j][0], acc[mi][j][1]);
                    *(float2*)&sm[off + 8 * 48] = make_float2(acc[mi][j][2], acc[mi][j][3]);
                }
            }
            __syncthreads();
        }

        // Gate epilogue: 128 rows x 16 j, 8 per thread (fixed col per thread).
        // Nonlinearities on MUFU.TANH: sigma(x) = 0.5 + 0.5*tanh(0.5x).
        const size_t gi_base = (size_t)(row_store * B_) * H3_;
        const size_t h_base  = (size_t)(row_store * B_) * H_;
        const int c = tid & 15;
        #pragma unroll
        for (int k = 0; k < 8; k++) {
            int r = (tid >> 4) + 16 * k;
            int bb = b0 + r;
            float hr_ = 0.f, hz = 0.f, hn = 0.f, hp = 0.f;
            if (tau > 0) {
                int base = R_GH + r * 48;
                hr_ = sm[base + c]      + sm[base + 6144 + c];
                hz  = sm[base + 16 + c] + sm[base + 6144 + 16 + c];
                hn  = sm[base + 32 + c] + sm[base + 6144 + 32 + c];
                hp  = hprev[(size_t)bb * H_ + jc];
            }
            size_t girow = gi_base + (size_t)bb * H3_;
            float ir  = GI[girow + jc];
            float iz  = GI[girow + H_ + jc];
            float inn = GI[girow + 2 * H_ + jc];
            float rg = 0.5f + 0.5f * tanhax(0.5f * (ir + hr_ + bias_r));
            float zg = 0.5f + 0.5f * tanhax(0.5f * (iz + hz + bias_z));
            float ng = tanhax(inn + bias_in + rg * (hn + bias_hn));
            float hnew = fmaf(zg, hp - ng, ng);
            Hst[h_base + (size_t)bb * H_ + jc] = hnew;
            Hrd[h_base + (size_t)bb * H_ + jc] = nvcuda::wmma::__float_to_tf32(hnew);
        }

        if (tau != S_ - 1) grid_barrier();
    }
}

// ---------------------------------------------------------------------------
extern "C" void kernel_launch(void* const* d_in, const int* in_sizes, int n_in,
                              void* d_out, int out_size) {
    const int*   slot_ids = (const int*)d_in[0];
    const float* value    = (const float*)d_in[1];
    const float* table    = (const float*)d_in[2];
    const float* Wih_f    = (const float*)d_in[3];
    const float* Whh_f    = (const float*)d_in[4];
    const float* bih_f    = (const float*)d_in[5];
    const float* bhh_f    = (const float*)d_in[6];
    const float* Wih_b    = (const float*)d_in[7];
    const float* Whh_b    = (const float*)d_in[8];
    const float* bih_b    = (const float*)d_in[9];
    const float* bhh_b    = (const float*)d_in[10];
    const float* Wproj    = (const float*)d_in[11];
    float* out = (float*)d_out;

    cudaFuncSetAttribute(mm_gemm_kernel<false>,
                         cudaFuncAttributeMaxDynamicSharedMemorySize, GSMEM_BYTES);
    cudaFuncSetAttribute(mm_gemm_kernel<true>,
                         cudaFuncAttributeMaxDynamicSharedMemorySize, GSMEM_BYTES);
    cudaFuncSetAttribute(gru_persistent_kernel,
                         cudaFuncAttributeMaxDynamicSharedMemorySize, PSMEM_BYTES);

    round_weights_kernel<<<(H3_ * DIN_ / 4 + 255) / 256, 256>>>(
        (const float4*)Wih_f, (const float4*)Wih_b, (const float4*)Wproj);
    build_x_kernel<<<M_, 256>>>(slot_ids, value, table);
    mm_gemm_kernel<false><<<dim3(H3_ / 256, M_ / 128, 2), 256, GSMEM_BYTES>>>(nullptr);
    gru_persistent_kernel<<<NCTA, 256, PSMEM_BYTES>>>(
        Whh_f, Whh_b, bih_f, bhh_f, bih_b, bhh_b);
    mm_gemm_kernel<true><<<dim3(E_ / 256, M_ / 128, 1), 256, GSMEM_BYTES>>>(out);
}

// round 10
// speedup vs baseline: 3.6724x; 1.1455x over previous
#include <cuda_runtime.h>
#include <mma.h>
#include <cstdint>

// Problem constants
#define B_    256
#define S_    64
#define DIN_  1024
#define H_    512
#define H3_   1536
#define E_    512
#define M_    (S_ * B_)   // 16384 rows (t*B + b)

// Scratch (device globals; no runtime allocation allowed)
__device__ float g_X[(size_t)M_ * DIN_];         // [t*B+b][1024]  (tf32-rounded)
__device__ float g_Wih[2][(size_t)H3_ * DIN_];   // tf32-rounded weights
__device__ float g_Wproj[(size_t)E_ * 2 * H_];   // tf32-rounded
__device__ float g_GI[2][(size_t)M_ * H3_];      // input-transform, per dir, NO bias
__device__ float g_Hbuf[2][(size_t)M_ * H_];     // fp32 GRU outputs (trajectory)
__device__ float g_Hr[2][(size_t)M_ * H_];       // tf32-rounded GRU outputs (GEMM input)

// Group barrier state: 4 groups (dir x b-half), 32 CTAs each. Padded lines.
__device__ volatile unsigned g_bar_cnt[4 * 32];
__device__ volatile unsigned g_bar_gen[4 * 32];

__device__ __forceinline__ void group_barrier(int grp) {
    __syncthreads();
    if (threadIdx.x == 0) {
        __threadfence();
        volatile unsigned* cnt = &g_bar_cnt[grp * 32];
        volatile unsigned* gen = &g_bar_gen[grp * 32];
        unsigned g = *gen;
        unsigned arrived = atomicAdd((unsigned*)cnt, 1u);
        if (arrived == 31) {
            *cnt = 0;
            __threadfence();
            atomicAdd((unsigned*)gen, 1u);
        } else {
            while (*gen == g) { __nanosleep(32); }
            __threadfence();
        }
    }
    __syncthreads();
}

// ---------------- low-level helpers ----------------
__device__ __forceinline__ void cp16s(uint32_t s, const void* g) {
    asm volatile("cp.async.cg.shared.global [%0], [%1], 16;\n" :: "r"(s), "l"(g));
}
__device__ __forceinline__ void cp_commit() {
    asm volatile("cp.async.commit_group;\n" ::);
}
template <int N> __device__ __forceinline__ void cp_wait() {
    asm volatile("cp.async.wait_group %0;\n" :: "n"(N));
}

__device__ __forceinline__ float4 tf32x4(float4 v) {
    v.x = nvcuda::wmma::__float_to_tf32(v.x); v.y = nvcuda::wmma::__float_to_tf32(v.y);
    v.z = nvcuda::wmma::__float_to_tf32(v.z); v.w = nvcuda::wmma::__float_to_tf32(v.w);
    return v;
}

__device__ __forceinline__ float tanhax(float x) {
    float y;
    asm("tanh.approx.f32 %0, %1;" : "=f"(y) : "f"(x));
    return y;
}

__device__ __forceinline__ void ldsm4(uint32_t& r0, uint32_t& r1, uint32_t& r2,
                                      uint32_t& r3, uint32_t addr) {
    asm volatile("ldmatrix.sync.aligned.m8n8.x4.shared.b16 {%0,%1,%2,%3}, [%4];"
                 : "=r"(r0), "=r"(r1), "=r"(r2), "=r"(r3) : "r"(addr));
}

__device__ __forceinline__ void mma8(float* d, const uint32_t* a,
                                     uint32_t b0, uint32_t b1) {
    asm volatile(
        "mma.sync.aligned.m16n8k8.row.col.f32.tf32.tf32.f32 "
        "{%0,%1,%2,%3},{%4,%5,%6,%7},{%8,%9},{%0,%1,%2,%3};"
        : "+f"(d[0]), "+f"(d[1]), "+f"(d[2]), "+f"(d[3])
        : "r"(a[0]), "r"(a[1]), "r"(a[2]), "r"(a[3]), "r"(b0), "r"(b1));
}

// ---------------------------------------------------------------------------
// Kernel 0: round weights to tf32 into scratch
// ---------------------------------------------------------------------------
__global__ void round_weights_kernel(const float4* __restrict__ wf,
                                     const float4* __restrict__ wb,
                                     const float4* __restrict__ wp) {
    const int NW = H3_ * DIN_ / 4;   // 393216
    const int NP = E_ * 2 * H_ / 4;  // 131072
    int i = blockIdx.x * blockDim.x + threadIdx.x;
    if (i < NW) {
        ((float4*)g_Wih[0])[i] = tf32x4(wf[i]);
        ((float4*)g_Wih[1])[i] = tf32x4(wb[i]);
        if (i < NP) ((float4*)g_Wproj)[i] = tf32x4(wp[i]);
    }
}

// ---------------------------------------------------------------------------
// Kernel 1: gather slot embedding + concat value embeds -> X (tf32-rounded)
// ---------------------------------------------------------------------------
__global__ void build_x_kernel(const int* __restrict__ slot_ids,
                               const float* __restrict__ value_embeds,
                               const float* __restrict__ embed_table) {
    int m = blockIdx.x;            // = t*B + b
    int t = m >> 8;
    int b = m & 255;
    int c4 = threadIdx.x;          // float4 column 0..255
    float4 v;
    if (c4 < 64) {
        int sid = slot_ids[b * S_ + t];
        v = ((const float4*)embed_table)[(size_t)sid * 64 + c4];
    } else {
        v = ((const float4*)value_embeds)[(size_t)(b * S_ + t) * 192 + (c4 - 64)];
    }
    ((float4*)g_X)[(size_t)m * 256 + c4] = tf32x4(v);
}

// ---------------------------------------------------------------------------
// Kernel 2/4: raw mma.sync tf32 GEMM, 3-stage cp.async, one sync per K-step.
// (unchanged from round 9)
// ---------------------------------------------------------------------------
#define GSMEM_BYTES 147456

template <bool PROJ>
__global__ __launch_bounds__(256, 1)
void mm_gemm_kernel(float* __restrict__ outp) {
    extern __shared__ __align__(128) float smem[];
    const uint32_t sbase = (uint32_t)__cvta_generic_to_shared(smem);
    const int tid  = threadIdx.x;
    const int lane = tid & 31;
    const int warp = tid >> 5;
    const int n0  = blockIdx.x * 256;
    const int m0  = blockIdx.y * 128;
    const int dir = blockIdx.z;

    const float* __restrict__ Wg = PROJ ? g_Wproj : g_Wih[dir];

    const int wm = (warp & 1) * 64;
    const int wn = (warp >> 1) * 64;

    const int a_rr = lane & 15;
    const int a_cs = lane >> 4;
    const int b_rr = (lane & 7) | ((lane & 16) >> 1);
    const int b_cs = (lane >> 3) & 1;

    float acc[4][8][4];
    #pragma unroll
    for (int i = 0; i < 4; i++)
        #pragma unroll
        for (int j = 0; j < 8; j++)
            #pragma unroll
            for (int e = 0; e < 4; e++) acc[i][j][e] = 0.0f;

    auto stage = [&](int s, int kt) {
        #pragma unroll
        for (int q = 0; q < 4; q++) {
            int id = tid + q * 256;
            int r = id >> 3, c8 = id & 7;
            const float* src;
            if (PROJ) {
                const float* hs = (kt < 16) ? g_Hr[0] : g_Hr[1];
                src = &hs[(size_t)(m0 + r) * H_ + (kt & 15) * 32 + c8 * 4];
            } else {
                src = &g_X[(size_t)(m0 + r) * DIN_ + kt * 32 + c8 * 4];
            }
            cp16s(sbase + s * 16384 + r * 128 + ((c8 ^ (r & 7)) << 4), src);
        }
        #pragma unroll
        for (int q = 0; q < 8; q++) {
            int id = tid + q * 256;
            int r = id >> 3, c8 = id & 7;
            cp16s(sbase + 49152 + s * 32768 + r * 128 + ((c8 ^ (r & 7)) << 4),
                  &Wg[(size_t)(n0 + r) * 1024 + kt * 32 + c8 * 4]);
        }
    };

    stage(0, 0); cp_commit();
    stage(1, 1); cp_commit();

    for (int kt = 0; kt < 32; kt++) {
        if (kt < 31) cp_wait<1>(); else cp_wait<0>();
        __syncthreads();
        if (kt + 2 < 32) { stage((kt + 2) % 3, kt + 2); cp_commit(); }

        const int s = kt % 3;
        const uint32_t sa = sbase + s * 16384;
        const uint32_t sb = sbase + 49152 + s * 32768;

        #pragma unroll
        for (int k8 = 0; k8 < 4; k8++) {
            uint32_t a[4][4];
            #pragma unroll
            for (int mi = 0; mi < 4; mi++) {
                int rr = wm + 16 * mi + a_rr;
                ldsm4(a[mi][0], a[mi][1], a[mi][2], a[mi][3],
                      sa + rr * 128 + (((2 * k8 + a_cs) ^ (rr & 7)) << 4));
            }
            #pragma unroll
            for (int g2 = 0; g2 < 4; g2++) {
                int rr = wn + 16 * g2 + b_rr;
                uint32_t b0, b1, b2, b3;
                ldsm4(b0, b1, b2, b3,
                      sb + rr * 128 + (((2 * k8 + b_cs) ^ (rr & 7)) << 4));
                #pragma unroll
                for (int mi = 0; mi < 4; mi++) {
                    mma8(acc[mi][2 * g2], a[mi], b0, b1);
                    mma8(acc[mi][2 * g2 + 1], a[mi], b2, b3);
                }
            }
        }
    }

    const int re = lane >> 2, ce = 2 * (lane & 3);
    #pragma unroll
    for (int mi = 0; mi < 4; mi++) {
        #pragma unroll
        for (int j = 0; j < 8; j++) {
            int row = m0 + wm + 16 * mi + re;
            int col = n0 + wn + 8 * j + ce;
            if (!PROJ) {
                float* C = g_GI[dir];
                *(float2*)&C[(size_t)row * H3_ + col] =
                    make_float2(acc[mi][j][0], acc[mi][j][1]);
                *(float2*)&C[(size_t)(row + 8) * H3_ + col] =
                    make_float2(acc[mi][j][2], acc[mi][j][3]);
            } else {
                int r1 = row, r2 = row + 8;
                size_t o1 = ((size_t)(r1 & 255) * S_ + (r1 >> 8)) * E_ + col;
                size_t o2 = ((size_t)(r2 & 255) * S_ + (r2 >> 8)) * E_ + col;
                *(float2*)&outp[o1] = make_float2(acc[mi][j][0], acc[mi][j][1]);
                *(float2*)&outp[o2] = make_float2(acc[mi][j][2], acc[mi][j][3]);
            }
        }
    }
}

// ---------------------------------------------------------------------------
// Kernel 3: PERSISTENT bidirectional GRU recurrence.
// 128 CTAs x 512 threads (16 warps = 8 M-slices x 2 K-halves).
// Group barriers: 4 groups of 32 CTAs (dir x b-half) — the true sync scope.
// GI + hprev prefetched into registers at step start (hidden under GEMM).
// SMEM floats: WSM 24576 | ASM 2x2x128x32=16384 | GH 2x128x48=12288 -> 208KB.
// ---------------------------------------------------------------------------
#define R_WSM 0
#define R_ASM 24576
#define R_GH  40960
#define PSMEM_BYTES (53248 * 4)

__global__ __launch_bounds__(512, 1)
void gru_persistent_kernel(const float* __restrict__ Whh_f,
                           const float* __restrict__ Whh_b,
                           const float* __restrict__ bih_f,
                           const float* __restrict__ bhh_f,
                           const float* __restrict__ bih_b,
                           const float* __restrict__ bhh_b) {
    extern __shared__ __align__(128) float sm[];
    const uint32_t sbase = (uint32_t)__cvta_generic_to_shared(sm);

    const int cta = blockIdx.x;
    const int dir = cta >> 6;
    const int rem = cta & 63;
    const int j0  = (rem >> 1) * 16;
    const int b0  = (rem & 1) * 128;
    const int grp = (dir << 1) | (rem & 1);

    const int tid  = threadIdx.x;
    const int lane = tid & 31;
    const int warp = tid >> 5;         // 0..15
    const int kh   = warp >> 3;        // K-half 0/1
    const int wm16 = (warp & 7) * 16;  // 16-row M slice

    const int a_rr = lane & 15;
    const int a_cs = lane >> 4;
    const int b_rr = (lane & 7) | ((lane & 16) >> 1);
    const int b_cs = (lane >> 3) & 1;

    const float* __restrict__ Whh = dir ? Whh_b : Whh_f;
    const float* __restrict__ bih = dir ? bih_b : bih_f;
    const float* __restrict__ bhh = dir ? bhh_b : bhh_f;
    float* __restrict__ GI  = g_GI[dir];
    float* __restrict__ Hst = g_Hbuf[dir];
    float* __restrict__ Hrd = g_Hr[dir];

    const int jc = j0 + (tid & 15);
    const int rbase = tid >> 4;        // 0..31; epilogue rows rbase + 32*k
    const float bias_r  = bih[jc]           + bhh[jc];
    const float bias_z  = bih[H_ + jc]      + bhh[H_ + jc];
    const float bias_in = bih[2 * H_ + jc];
    const float bias_hn = bhh[2 * H_ + jc];

    // Load Whh slice: rows = gate*16+jl (48), k-chunked SW128 layout, tf32.
    for (int idx = tid; idx < 6144; idx += 512) {
        int row = idx >> 7;          // 0..47
        int f4c = idx & 127;
        int kc = f4c >> 3, c8 = f4c & 7;
        int g = row >> 4, jl = row & 15;
        float4 v = tf32x4(*(const float4*)
            &Whh[((size_t)(g * H_ + j0 + jl)) * H_ + kc * 32 + c8 * 4]);
        *(float4*)&sm[R_WSM + (kc * 48 + row) * 32 + ((c8 ^ (row & 7)) << 2)] = v;
    }
    __syncthreads();

    for (int tau = 0; tau < S_; tau++) {
        const int row_store = dir ? (S_ - 1 - tau) : tau;
        const int row_prev  = dir ? (S_ - tau)     : (tau - 1);
        const float* __restrict__ hprev =
            (tau > 0) ? &Hst[(size_t)row_prev * B_ * H_] : nullptr;

        // ---- Prefetch epilogue operands (independent LDGs, hidden by GEMM)
        float pir[4], piz[4], pinn[4], php[4];
        {
            const size_t gi_base = (size_t)(row_store * B_) * H3_;
            #pragma unroll
            for (int k = 0; k < 4; k++) {
                int bb = b0 + rbase + 32 * k;
                size_t girow = gi_base + (size_t)bb * H3_;
                pir[k]  = GI[girow + jc];
                piz[k]  = GI[girow + H_ + jc];
                pinn[k] = GI[girow + 2 * H_ + jc];
                php[k]  = (tau > 0) ? hprev[(size_t)bb * H_ + jc] : 0.0f;
            }
        }

        if (tau > 0) {
            const float* __restrict__ hr = &Hrd[(size_t)row_prev * B_ * H_];

            float acc[6][4];
            #pragma unroll
            for (int j = 0; j < 6; j++)
                #pragma unroll
                for (int e = 0; e < 4; e++) acc[j][e] = 0.0f;

            auto stage = [&](int s, int i) {
                #pragma unroll
                for (int q = 0; q < 4; q++) {
                    int id = tid + q * 512;       // 0..2047
                    int khs = id >> 10;           // 0/1
                    int r = (id >> 3) & 127, c8 = id & 7;
                    int kc = khs * 8 + i;
                    cp16s(sbase + 4 * (R_ASM + ((s * 2 + khs) * 128 + r) * 32)
                              + ((c8 ^ (r & 7)) << 4),
                          &hr[(size_t)(b0 + r) * H_ + kc * 32 + c8 * 4]);
                }
            };

            stage(0, 0); cp_commit();
            stage(1, 1); cp_commit();

            for (int i = 0; i < 8; i++) {
                const int s = i & 1;
                if (i < 7) cp_wait<1>(); else cp_wait<0>();
                __syncthreads();
                const uint32_t sa = sbase + 4 * (R_ASM + (s * 2 + kh) * 128 * 32);
                const int kc = kh * 8 + i;
                const uint32_t wb = sbase + 4 * (R_WSM + kc * 48 * 32);

                #pragma unroll
                for (int k8 = 0; k8 < 4; k8++) {
                    uint32_t a[4];
                    int rr = wm16 + a_rr;
                    ldsm4(a[0], a[1], a[2], a[3],
                          sa + rr * 128 + (((2 * k8 + a_cs) ^ (rr & 7)) << 4));
                    #pragma unroll
                    for (int g2 = 0; g2 < 3; g2++) {
                        int br = 16 * g2 + b_rr;
                        uint32_t bb0, bb1, bb2, bb3;
                        ldsm4(bb0, bb1, bb2, bb3,
                              wb + br * 128 + (((2 * k8 + b_cs) ^ (br & 7)) << 4));
                        mma8(acc[2 * g2], a, bb0, bb1);
                        mma8(acc[2 * g2 + 1], a, bb2, bb3);
                    }
                }
                __syncthreads();
                if (i + 2 < 8) { stage(s, i + 2); cp_commit(); }
            }

            // Write partials to GH[kh]
            const int re = lane >> 2, ce = 2 * (lane & 3);
            #pragma unroll
            for (int j = 0; j < 6; j++) {
                int row = wm16 + re;
                int col = 8 * j + ce;
                int off = R_GH + kh * 6144 + row * 48 + col;
                *(float2*)&sm[off] = make_float2(acc[j][0], acc[j][1]);
                *(float2*)&sm[off + 8 * 48] = make_float2(acc[j][2], acc[j][3]);
            }
            __syncthreads();
        }

        // Gate epilogue: 128 rows x 16 j, 4 per thread; operands prefetched.
        const size_t h_base = (size_t)(row_store * B_) * H_;
        const int c = tid & 15;
        #pragma unroll
        for (int k = 0; k < 4; k++) {
            int r = rbase + 32 * k;
            int bb = b0 + r;
            float hr_ = 0.f, hz = 0.f, hn = 0.f;
            if (tau > 0) {
                int base = R_GH + r * 48;
                hr_ = sm[base + c]      + sm[base + 6144 + c];
                hz  = sm[base + 16 + c] + sm[base + 6144 + 16 + c];
                hn  = sm[base + 32 + c] + sm[base + 6144 + 32 + c];
            }
            float rg = 0.5f + 0.5f * tanhax(0.5f * (pir[k] + hr_ + bias_r));
            float zg = 0.5f + 0.5f * tanhax(0.5f * (piz[k] + hz + bias_z));
            float ng = tanhax(pinn[k] + bias_in + rg * (hn + bias_hn));
            float hnew = fmaf(zg, php[k] - ng, ng);
            Hst[h_base + (size_t)bb * H_ + jc] = hnew;
            Hrd[h_base + (size_t)bb * H_ + jc] = nvcuda::wmma::__float_to_tf32(hnew);
        }

        if (tau != S_ - 1) group_barrier(grp);
    }
}

// ---------------------------------------------------------------------------
extern "C" void kernel_launch(void* const* d_in, const int* in_sizes, int n_in,
                              void* d_out, int out_size) {
    const int*   slot_ids = (const int*)d_in[0];
    const float* value    = (const float*)d_in[1];
    const float* table    = (const float*)d_in[2];
    const float* Wih_f    = (const float*)d_in[3];
    const float* Whh_f    = (const float*)d_in[4];
    const float* bih_f    = (const float*)d_in[5];
    const float* bhh_f    = (const float*)d_in[6];
    const float* Wih_b    = (const float*)d_in[7];
    const float* Whh_b    = (const float*)d_in[8];
    const float* bih_b    = (const float*)d_in[9];
    const float* bhh_b    = (const float*)d_in[10];
    const float* Wproj    = (const float*)d_in[11];
    float* out = (float*)d_out;

    cudaFuncSetAttribute(mm_gemm_kernel<false>,
                         cudaFuncAttributeMaxDynamicSharedMemorySize, GSMEM_BYTES);
    cudaFuncSetAttribute(mm_gemm_kernel<true>,
                         cudaFuncAttributeMaxDynamicSharedMemorySize, GSMEM_BYTES);
    cudaFuncSetAttribute(gru_persistent_kernel,
                         cudaFuncAttributeMaxDynamicSharedMemorySize, PSMEM_BYTES);

    round_weights_kernel<<<(H3_ * DIN_ / 4 + 255) / 256, 256>>>(
        (const float4*)Wih_f, (const float4*)Wih_b, (const float4*)Wproj);
    build_x_kernel<<<M_, 256>>>(slot_ids, value, table);
    mm_gemm_kernel<false><<<dim3(H3_ / 256, M_ / 128, 2), 256, GSMEM_BYTES>>>(nullptr);
    gru_persistent_kernel<<<128, 512, PSMEM_BYTES>>>(
        Whh_f, Whh_b, bih_f, bhh_f, bih_b, bhh_b);
    mm_gemm_kernel<true><<<dim3(E_ / 256, M_ / 128, 1), 256, GSMEM_BYTES>>>(out);
}

// round 11
// speedup vs baseline: 3.9188x; 1.0671x over previous
#include <cuda_runtime.h>
#include <mma.h>
#include <cstdint>

// Problem constants
#define B_    256
#define S_    64
#define DIN_  1024
#define H_    512
#define H3_   1536
#define E_    512
#define M_    (S_ * B_)   // 16384 rows (t*B + b)

// Scratch (device globals; no runtime allocation allowed)
__device__ float g_X[(size_t)M_ * DIN_];         // [t*B+b][1024]  (tf32-rounded)
__device__ float g_Wih[2][(size_t)H3_ * DIN_];   // tf32-rounded weights
__device__ float g_Wproj[(size_t)E_ * 2 * H_];   // tf32-rounded
__device__ float g_GI[2][(size_t)M_ * H3_];      // input-transform, per dir, NO bias
__device__ float g_Hbuf[2][(size_t)M_ * H_];     // fp32 GRU outputs (trajectory)
__device__ float g_Hr[2][(size_t)M_ * H_];       // tf32-rounded GRU outputs (GEMM input)

// Group barrier state: 4 groups (dir x b-half), 32 CTAs each. Padded lines.
__device__ volatile unsigned g_bar_cnt[4 * 32];
__device__ volatile unsigned g_bar_gen[4 * 32];

// ---------------- low-level helpers ----------------
__device__ __forceinline__ void cp16s(uint32_t s, const void* g) {
    asm volatile("cp.async.cg.shared.global [%0], [%1], 16;\n" :: "r"(s), "l"(g));
}
__device__ __forceinline__ void cp_commit() {
    asm volatile("cp.async.commit_group;\n" ::);
}
template <int N> __device__ __forceinline__ void cp_wait() {
    asm volatile("cp.async.wait_group %0;\n" :: "n"(N));
}

__device__ __forceinline__ float4 tf32x4(float4 v) {
    v.x = nvcuda::wmma::__float_to_tf32(v.x); v.y = nvcuda::wmma::__float_to_tf32(v.y);
    v.z = nvcuda::wmma::__float_to_tf32(v.z); v.w = nvcuda::wmma::__float_to_tf32(v.w);
    return v;
}

__device__ __forceinline__ float tanhax(float x) {
    float y;
    asm("tanh.approx.f32 %0, %1;" : "=f"(y) : "f"(x));
    return y;
}

__device__ __forceinline__ void ldsm4(uint32_t& r0, uint32_t& r1, uint32_t& r2,
                                      uint32_t& r3, uint32_t addr) {
    asm volatile("ldmatrix.sync.aligned.m8n8.x4.shared.b16 {%0,%1,%2,%3}, [%4];"
                 : "=r"(r0), "=r"(r1), "=r"(r2), "=r"(r3) : "r"(addr));
}

__device__ __forceinline__ void mma8(float* d, const uint32_t* a,
                                     uint32_t b0, uint32_t b1) {
    asm volatile(
        "mma.sync.aligned.m16n8k8.row.col.f32.tf32.tf32.f32 "
        "{%0,%1,%2,%3},{%4,%5,%6,%7},{%8,%9},{%0,%1,%2,%3};"
        : "+f"(d[0]), "+f"(d[1]), "+f"(d[2]), "+f"(d[3])
        : "r"(a[0]), "r"(a[1]), "r"(a[2]), "r"(a[3]), "r"(b0), "r"(b1));
}

// ---------------------------------------------------------------------------
// Kernel 0: round weights to tf32 into scratch
// ---------------------------------------------------------------------------
__global__ void round_weights_kernel(const float4* __restrict__ wf,
                                     const float4* __restrict__ wb,
                                     const float4* __restrict__ wp) {
    const int NW = H3_ * DIN_ / 4;   // 393216
    const int NP = E_ * 2 * H_ / 4;  // 131072
    int i = blockIdx.x * blockDim.x + threadIdx.x;
    if (i < NW) {
        ((float4*)g_Wih[0])[i] = tf32x4(wf[i]);
        ((float4*)g_Wih[1])[i] = tf32x4(wb[i]);
        if (i < NP) ((float4*)g_Wproj)[i] = tf32x4(wp[i]);
    }
}

// ---------------------------------------------------------------------------
// Kernel 1: gather slot embedding + concat value embeds -> X (tf32-rounded)
// ---------------------------------------------------------------------------
__global__ void build_x_kernel(const int* __restrict__ slot_ids,
                               const float* __restrict__ value_embeds,
                               const float* __restrict__ embed_table) {
    int m = blockIdx.x;            // = t*B + b
    int t = m >> 8;
    int b = m & 255;
    int c4 = threadIdx.x;          // float4 column 0..255
    float4 v;
    if (c4 < 64) {
        int sid = slot_ids[b * S_ + t];
        v = ((const float4*)embed_table)[(size_t)sid * 64 + c4];
    } else {
        v = ((const float4*)value_embeds)[(size_t)(b * S_ + t) * 192 + (c4 - 64)];
    }
    ((float4*)g_X)[(size_t)m * 256 + c4] = tf32x4(v);
}

// ---------------------------------------------------------------------------
// Kernel 2/4: raw mma.sync tf32 GEMM, 512 threads (16 warps = 4M x 4N),
// warp tile 32x64, 3-stage cp.async, ONE sync per K-step.
//   PROJ=false: GI[dir] = X @ Wih[dir]^T   (M=16384, N=1536, K=1024)
//   PROJ=true:  out = concat(Hf,Hb) @ Wproj^T, stored transposed to [B][S][E]
// SMEM: A[3][128][32] @0 (48KB), B[3][256][32] @48KB (96KB). Total 144KB.
// ---------------------------------------------------------------------------
#define GSMEM_BYTES 147456

template <bool PROJ>
__global__ __launch_bounds__(512, 1)
void mm_gemm_kernel(float* __restrict__ outp) {
    extern __shared__ __align__(128) float smem[];
    const uint32_t sbase = (uint32_t)__cvta_generic_to_shared(smem);
    const int tid  = threadIdx.x;
    const int lane = tid & 31;
    const int warp = tid >> 5;          // 0..15
    const int n0  = blockIdx.x * 256;
    const int m0  = blockIdx.y * 128;
    const int dir = blockIdx.z;

    const float* __restrict__ Wg = PROJ ? g_Wproj : g_Wih[dir];

    const int wm = (warp & 3) * 32;
    const int wn = (warp >> 2) * 64;

    const int a_rr = lane & 15;
    const int a_cs = lane >> 4;
    const int b_rr = (lane & 7) | ((lane & 16) >> 1);
    const int b_cs = (lane >> 3) & 1;

    float acc[2][8][4];
    #pragma unroll
    for (int i = 0; i < 2; i++)
        #pragma unroll
        for (int j = 0; j < 8; j++)
            #pragma unroll
            for (int e = 0; e < 4; e++) acc[i][j][e] = 0.0f;

    auto stage = [&](int s, int kt) {
        #pragma unroll
        for (int q = 0; q < 2; q++) {            // A: 1024 cp16
            int id = tid + q * 512;
            int r = id >> 3, c8 = id & 7;
            const float* src;
            if (PROJ) {
                const float* hs = (kt < 16) ? g_Hr[0] : g_Hr[1];
                src = &hs[(size_t)(m0 + r) * H_ + (kt & 15) * 32 + c8 * 4];
            } else {
                src = &g_X[(size_t)(m0 + r) * DIN_ + kt * 32 + c8 * 4];
            }
            cp16s(sbase + s * 16384 + r * 128 + ((c8 ^ (r & 7)) << 4), src);
        }
        #pragma unroll
        for (int q = 0; q < 4; q++) {            // B: 2048 cp16
            int id = tid + q * 512;
            int r = id >> 3, c8 = id & 7;
            cp16s(sbase + 49152 + s * 32768 + r * 128 + ((c8 ^ (r & 7)) << 4),
                  &Wg[(size_t)(n0 + r) * 1024 + kt * 32 + c8 * 4]);
        }
    };

    stage(0, 0); cp_commit();
    stage(1, 1); cp_commit();

    for (int kt = 0; kt < 32; kt++) {
        if (kt < 31) cp_wait<1>(); else cp_wait<0>();
        __syncthreads();
        if (kt + 2 < 32) { stage((kt + 2) % 3, kt + 2); cp_commit(); }

        const int s = kt % 3;
        const uint32_t sa = sbase + s * 16384;
        const uint32_t sb = sbase + 49152 + s * 32768;

        #pragma unroll
        for (int k8 = 0; k8 < 4; k8++) {
            uint32_t a[2][4];
            #pragma unroll
            for (int mi = 0; mi < 2; mi++) {
                int rr = wm + 16 * mi + a_rr;
                ldsm4(a[mi][0], a[mi][1], a[mi][2], a[mi][3],
                      sa + rr * 128 + (((2 * k8 + a_cs) ^ (rr & 7)) << 4));
            }
            #pragma unroll
            for (int g2 = 0; g2 < 4; g2++) {
                int rr = wn + 16 * g2 + b_rr;
                uint32_t b0, b1, b2, b3;
                ldsm4(b0, b1, b2, b3,
                      sb + rr * 128 + (((2 * k8 + b_cs) ^ (rr & 7)) << 4));
                #pragma unroll
                for (int mi = 0; mi < 2; mi++) {
                    mma8(acc[mi][2 * g2], a[mi], b0, b1);
                    mma8(acc[mi][2 * g2 + 1], a[mi], b2, b3);
                }
            }
        }
    }

    const int re = lane >> 2, ce = 2 * (lane & 3);
    #pragma unroll
    for (int mi = 0; mi < 2; mi++) {
        #pragma unroll
        for (int j = 0; j < 8; j++) {
            int row = m0 + wm + 16 * mi + re;
            int col = n0 + wn + 8 * j + ce;
            if (!PROJ) {
                float* C = g_GI[dir];
                *(float2*)&C[(size_t)row * H3_ + col] =
                    make_float2(acc[mi][j][0], acc[mi][j][1]);
                *(float2*)&C[(size_t)(row + 8) * H3_ + col] =
                    make_float2(acc[mi][j][2], acc[mi][j][3]);
            } else {
                int r1 = row, r2 = row + 8;
                size_t o1 = ((size_t)(r1 & 255) * S_ + (r1 >> 8)) * E_ + col;
                size_t o2 = ((size_t)(r2 & 255) * S_ + (r2 >> 8)) * E_ + col;
                *(float2*)&outp[o1] = make_float2(acc[mi][j][0], acc[mi][j][1]);
                *(float2*)&outp[o2] = make_float2(acc[mi][j][2], acc[mi][j][3]);
            }
        }
    }
}

// ---------------------------------------------------------------------------
// Kernel 3: PERSISTENT bidirectional GRU recurrence.
// 128 CTAs x 512 threads (16 warps = 8 M-slices x 2 K-halves).
// 3-stage K-loop (1 sync/iter). GH overlays ASM (disjoint lifetimes, guarded).
// Split-phase group barrier with next-step GI prefetch under the wait.
// SMEM floats: WSM 24576 @0 | ASM 3x2x128x32 = 24576 @24576 | GH overlays ASM.
// Total 49152 floats = 192KB.
// ---------------------------------------------------------------------------
#define R_WSM 0
#define R_ASM 24576
#define R_GH  24576
#define PSMEM_BYTES (49152 * 4)

__global__ __launch_bounds__(512, 1)
void gru_persistent_kernel(const float* __restrict__ Whh_f,
                           const float* __restrict__ Whh_b,
                           const float* __restrict__ bih_f,
                           const float* __restrict__ bhh_f,
                           const float* __restrict__ bih_b,
                           const float* __restrict__ bhh_b) {
    extern __shared__ __align__(128) float sm[];
    const uint32_t sbase = (uint32_t)__cvta_generic_to_shared(sm);

    const int cta = blockIdx.x;
    const int dir = cta >> 6;
    const int rem = cta & 63;
    const int j0  = (rem >> 1) * 16;
    const int b0  = (rem & 1) * 128;
    const int grp = (dir << 1) | (rem & 1);
    volatile unsigned* bar_cnt = &g_bar_cnt[grp * 32];
    volatile unsigned* bar_gen = &g_bar_gen[grp * 32];

    const int tid  = threadIdx.x;
    const int lane = tid & 31;
    const int warp = tid >> 5;         // 0..15
    const int kh   = warp >> 3;        // K-half 0/1
    const int wm16 = (warp & 7) * 16;  // 16-row M slice

    const int a_rr = lane & 15;
    const int a_cs = lane >> 4;
    const int b_rr = (lane & 7) | ((lane & 16) >> 1);
    const int b_cs = (lane >> 3) & 1;

    const float* __restrict__ Whh = dir ? Whh_b : Whh_f;
    const float* __restrict__ bih = dir ? bih_b : bih_f;
    const float* __restrict__ bhh = dir ? bhh_b : bhh_f;
    float* __restrict__ GI  = g_GI[dir];
    float* __restrict__ Hst = g_Hbuf[dir];
    float* __restrict__ Hrd = g_Hr[dir];

    const int jc = j0 + (tid & 15);
    const int rbase = tid >> 4;        // 0..31; epilogue rows rbase + 32*k
    const float bias_r  = bih[jc]           + bhh[jc];
    const float bias_z  = bih[H_ + jc]      + bhh[H_ + jc];
    const float bias_in = bih[2 * H_ + jc];
    const float bias_hn = bhh[2 * H_ + jc];

    // Load Whh slice: rows = gate*16+jl (48), k-chunked SW128 layout, tf32.
    for (int idx = tid; idx < 6144; idx += 512) {
        int row = idx >> 7;          // 0..47
        int f4c = idx & 127;
        int kc = f4c >> 3, c8 = f4c & 7;
        int g = row >> 4, jl = row & 15;
        float4 v = tf32x4(*(const float4*)
            &Whh[((size_t)(g * H_ + j0 + jl)) * H_ + kc * 32 + c8 * 4]);
        *(float4*)&sm[R_WSM + (kc * 48 + row) * 32 + ((c8 ^ (row & 7)) << 2)] = v;
    }
    __syncthreads();

    // Prefetch GI for tau = 0.
    float pir[4], piz[4], pinn[4];
    {
        const int rs0 = dir ? (S_ - 1) : 0;
        const size_t gi_base = (size_t)(rs0 * B_) * H3_;
        #pragma unroll
        for (int k = 0; k < 4; k++) {
            size_t girow = gi_base + (size_t)(b0 + rbase + 32 * k) * H3_;
            pir[k]  = GI[girow + jc];
            piz[k]  = GI[girow + H_ + jc];
            pinn[k] = GI[girow + 2 * H_ + jc];
        }
    }

    for (int tau = 0; tau < S_; tau++) {
        const int row_store = dir ? (S_ - 1 - tau) : tau;
        const int row_prev  = dir ? (S_ - tau)     : (tau - 1);
        const float* __restrict__ hprev =
            (tau > 0) ? &Hst[(size_t)row_prev * B_ * H_] : nullptr;

        // hp prefetch (independent LDGs, hidden by the GEMM below)
        float php[4];
        #pragma unroll
        for (int k = 0; k < 4; k++)
            php[k] = (tau > 0) ? hprev[(size_t)(b0 + rbase + 32 * k) * H_ + jc] : 0.0f;

        if (tau > 0) {
            const float* __restrict__ hr = &Hrd[(size_t)row_prev * B_ * H_];

            float acc[6][4];
            #pragma unroll
            for (int j = 0; j < 6; j++)
                #pragma unroll
                for (int e = 0; e < 4; e++) acc[j][e] = 0.0f;

            auto stage = [&](int s, int i) {
                #pragma unroll
                for (int q = 0; q < 4; q++) {
                    int id = tid + q * 512;       // 0..2047
                    int khs = id >> 10;           // 0/1
                    int r = (id >> 3) & 127, c8 = id & 7;
                    int kc = khs * 8 + i;
                    cp16s(sbase + 4 * (R_ASM + ((s * 2 + khs) * 128 + r) * 32)
                              + ((c8 ^ (r & 7)) << 4),
                          &hr[(size_t)(b0 + r) * H_ + kc * 32 + c8 * 4]);
                }
            };

            stage(0, 0); cp_commit();
            stage(1, 1); cp_commit();

            for (int i = 0; i < 8; i++) {
                if (i < 7) cp_wait<1>(); else cp_wait<0>();
                __syncthreads();
                if (i + 2 < 8) { stage((i + 2) % 3, i + 2); cp_commit(); }

                const int sbuf = i % 3;
                const uint32_t sa = sbase + 4 * (R_ASM + (sbuf * 2 + kh) * 128 * 32);
                const int kc = kh * 8 + i;
                const uint32_t wb = sbase + 4 * (R_WSM + kc * 48 * 32);

                #pragma unroll
                for (int k8 = 0; k8 < 4; k8++) {
                    uint32_t a[4];
                    int rr = wm16 + a_rr;
                    ldsm4(a[0], a[1], a[2], a[3],
                          sa + rr * 128 + (((2 * k8 + a_cs) ^ (rr & 7)) << 4));
                    #pragma unroll
                    for (int g2 = 0; g2 < 3; g2++) {
                        int br = 16 * g2 + b_rr;
                        uint32_t bb0, bb1, bb2, bb3;
                        ldsm4(bb0, bb1, bb2, bb3,
                              wb + br * 128 + (((2 * k8 + b_cs) ^ (br & 7)) << 4));
                        mma8(acc[2 * g2], a, bb0, bb1);
                        mma8(acc[2 * g2 + 1], a, bb2, bb3);
                    }
                }
            }
            __syncthreads();   // all reads of ASM done before GH overlay writes

            // Write partials to GH[kh] (overlays ASM stages 0/1)
            const int re = lane >> 2, ce = 2 * (lane & 3);
            #pragma unroll
            for (int j = 0; j < 6; j++) {
                int row = wm16 + re;
                int col = 8 * j + ce;
                int off = R_GH + kh * 6144 + row * 48 + col;
                *(float2*)&sm[off] = make_float2(acc[j][0], acc[j][1]);
                *(float2*)&sm[off + 8 * 48] = make_float2(acc[j][2], acc[j][3]);
            }
            __syncthreads();
        }

        // Gate epilogue: 128 rows x 16 j, 4 per thread; operands prefetched.
        const size_t h_base = (size_t)(row_store * B_) * H_;
        const int c = tid & 15;
        #pragma unroll
        for (int k = 0; k < 4; k++) {
            int r = rbase + 32 * k;
            int bb = b0 + r;
            float hr_ = 0.f, hz = 0.f, hn = 0.f;
            if (tau > 0) {
                int base = R_GH + r * 48;
                hr_ = sm[base + c]      + sm[base + 6144 + c];
                hz  = sm[base + 16 + c] + sm[base + 6144 + 16 + c];
                hn  = sm[base + 32 + c] + sm[base + 6144 + 32 + c];
            }
            float rg = 0.5f + 0.5f * tanhax(0.5f * (pir[k] + hr_ + bias_r));
            float zg = 0.5f + 0.5f * tanhax(0.5f * (piz[k] + hz + bias_z));
            float ng = tanhax(pinn[k] + bias_in + rg * (hn + bias_hn));
            float hnew = fmaf(zg, php[k] - ng, ng);
            Hst[h_base + (size_t)bb * H_ + jc] = hnew;
            Hrd[h_base + (size_t)bb * H_ + jc] = nvcuda::wmma::__float_to_tf32(hnew);
        }

        // Split-phase barrier: arrive -> prefetch next GI -> wait.
        if (tau != S_ - 1) {
            __syncthreads();           // all stores issued
            unsigned g = 0, a = 0;
            if (tid == 0) {
                __threadfence();
                g = *bar_gen;
                a = atomicAdd((unsigned*)bar_cnt, 1u);
                if (a == 31) {
                    *bar_cnt = 0;
                    __threadfence();
                    atomicAdd((unsigned*)bar_gen, 1u);
                }
            }
            // Prefetch GI for tau+1 (independent of h) under the barrier wait
            {
                const int rs1 = dir ? (S_ - 2 - tau) : (tau + 1);
                const size_t gi_base = (size_t)(rs1 * B_) * H3_;
                #pragma unroll
                for (int k = 0; k < 4; k++) {
                    size_t girow = gi_base + (size_t)(b0 + rbase + 32 * k) * H3_;
                    pir[k]  = GI[girow + jc];
                    piz[k]  = GI[girow + H_ + jc];
                    pinn[k] = GI[girow + 2 * H_ + jc];
                }
            }
            if (tid == 0 && a != 31) {
                while (*bar_gen == g) { }
                __threadfence();
            }
            __syncthreads();
        }
    }
}

// ---------------------------------------------------------------------------
extern "C" void kernel_launch(void* const* d_in, const int* in_sizes, int n_in,
                              void* d_out, int out_size) {
    const int*   slot_ids = (const int*)d_in[0];
    const float* value    = (const float*)d_in[1];
    const float* table    = (const float*)d_in[2];
    const float* Wih_f    = (const float*)d_in[3];
    const float* Whh_f    = (const float*)d_in[4];
    const float* bih_f    = (const float*)d_in[5];
    const float* bhh_f    = (const float*)d_in[6];
    const float* Wih_b    = (const float*)d_in[7];
    const float* Whh_b    = (const float*)d_in[8];
    const float* bih_b    = (const float*)d_in[9];
    const float* bhh_b    = (const float*)d_in[10];
    const float* Wproj    = (const float*)d_in[11];
    float* out = (float*)d_out;

    cudaFuncSetAttribute(mm_gemm_kernel<false>,
                         cudaFuncAttributeMaxDynamicSharedMemorySize, GSMEM_BYTES);
    cudaFuncSetAttribute(mm_gemm_kernel<true>,
                         cudaFuncAttributeMaxDynamicSharedMemorySize, GSMEM_BYTES);
    cudaFuncSetAttribute(gru_persistent_kernel,
                         cudaFuncAttributeMaxDynamicSharedMemorySize, PSMEM_BYTES);

    round_weights_kernel<<<(H3_ * DIN_ / 4 + 255) / 256, 256>>>(
        (const float4*)Wih_f, (const float4*)Wih_b, (const float4*)Wproj);
    build_x_kernel<<<M_, 256>>>(slot_ids, value, table);
    mm_gemm_kernel<false><<<dim3(H3_ / 256, M_ / 128, 2), 512, GSMEM_BYTES>>>(nullptr);
    gru_persistent_kernel<<<128, 512, PSMEM_BYTES>>>(
        Whh_f, Whh_b, bih_f, bhh_f, bih_b, bhh_b);
    mm_gemm_kernel<true><<<dim3(E_ / 256, M_ / 128, 1), 512, GSMEM_BYTES>>>(out);
}

// round 12
// speedup vs baseline: 6.3554x; 1.6218x over previous
#include <cuda_runtime.h>
#include <cuda_fp16.h>
#include <cstdint>

// Problem constants
#define B_    256
#define S_    64
#define DIN_  1024
#define H_    512
#define H3_   1536
#define E_    512
#define M_    (S_ * B_)   // 16384 rows (t*B + b)

// Scratch (device globals; no runtime allocation allowed)
__device__ __half g_Xh[(size_t)M_ * DIN_];        // fp16 inputs for GEMM
__device__ __half g_Wih_h[2][(size_t)H3_ * DIN_]; // fp16 weights
__device__ __half g_Wproj_h[(size_t)E_ * 2 * H_];
__device__ float  g_GI[2][(size_t)M_ * H3_];      // input-transform, fp32
__device__ float  g_Hbuf[2][(size_t)M_ * H_];     // fp32 GRU trajectory
__device__ __half g_Hh[2][(size_t)M_ * H_];       // fp16 GRU outputs (GEMM input)

// Group barrier state: 4 groups (dir x b-half), 32 CTAs each. Padded lines.
__device__ volatile unsigned g_bar_cnt[4 * 32];
__device__ volatile unsigned g_bar_gen[4 * 32];

// ---------------- low-level helpers ----------------
__device__ __forceinline__ void cp16s(uint32_t s, const void* g) {
    asm volatile("cp.async.cg.shared.global [%0], [%1], 16;\n" :: "r"(s), "l"(g));
}
__device__ __forceinline__ void cp_commit() {
    asm volatile("cp.async.commit_group;\n" ::);
}
template <int N> __device__ __forceinline__ void cp_wait() {
    asm volatile("cp.async.wait_group %0;\n" :: "n"(N));
}

__device__ __forceinline__ uint2 f4h(float4 v) {
    __half2 a = __floats2half2_rn(v.x, v.y);
    __half2 b = __floats2half2_rn(v.z, v.w);
    uint2 r;
    r.x = *reinterpret_cast<uint32_t*>(&a);
    r.y = *reinterpret_cast<uint32_t*>(&b);
    return r;
}

__device__ __forceinline__ float tanhax(float x) {
    float y;
    asm("tanh.approx.f32 %0, %1;" : "=f"(y) : "f"(x));
    return y;
}

__device__ __forceinline__ void ldsm4(uint32_t& r0, uint32_t& r1, uint32_t& r2,
                                      uint32_t& r3, uint32_t addr) {
    asm volatile("ldmatrix.sync.aligned.m8n8.x4.shared.b16 {%0,%1,%2,%3}, [%4];"
                 : "=r"(r0), "=r"(r1), "=r"(r2), "=r"(r3) : "r"(addr));
}

// fp16 MMA, fp32 accumulate: D[16x8] += A[16x16] * B[16x8]
__device__ __forceinline__ void mma16(float* d, const uint32_t* a,
                                      uint32_t b0, uint32_t b1) {
    asm volatile(
        "mma.sync.aligned.m16n8k16.row.col.f32.f16.f16.f32 "
        "{%0,%1,%2,%3},{%4,%5,%6,%7},{%8,%9},{%0,%1,%2,%3};"
        : "+f"(d[0]), "+f"(d[1]), "+f"(d[2]), "+f"(d[3])
        : "r"(a[0]), "r"(a[1]), "r"(a[2]), "r"(a[3]), "r"(b0), "r"(b1));
}

// ---------------------------------------------------------------------------
// Kernel 0: convert weights to fp16 scratch
// ---------------------------------------------------------------------------
__global__ void round_weights_kernel(const float4* __restrict__ wf,
                                     const float4* __restrict__ wb,
                                     const float4* __restrict__ wp) {
    const int NW = H3_ * DIN_ / 4;   // 393216
    const int NP = E_ * 2 * H_ / 4;  // 131072
    int i = blockIdx.x * blockDim.x + threadIdx.x;
    if (i < NW) {
        ((uint2*)g_Wih_h[0])[i] = f4h(wf[i]);
        ((uint2*)g_Wih_h[1])[i] = f4h(wb[i]);
        if (i < NP) ((uint2*)g_Wproj_h)[i] = f4h(wp[i]);
    }
}

// ---------------------------------------------------------------------------
// Kernel 1: gather slot embedding + concat value embeds -> Xh (fp16)
// ---------------------------------------------------------------------------
__global__ void build_x_kernel(const int* __restrict__ slot_ids,
                               const float* __restrict__ value_embeds,
                               const float* __restrict__ embed_table) {
    int m = blockIdx.x;            // = t*B + b
    int t = m >> 8;
    int b = m & 255;
    int c4 = threadIdx.x;          // float4 column 0..255
    float4 v;
    if (c4 < 64) {
        int sid = slot_ids[b * S_ + t];
        v = ((const float4*)embed_table)[(size_t)sid * 64 + c4];
    } else {
        v = ((const float4*)value_embeds)[(size_t)(b * S_ + t) * 192 + (c4 - 64)];
    }
    ((uint2*)g_Xh)[(size_t)m * 256 + c4] = f4h(v);
}

// ---------------------------------------------------------------------------
// Kernel 2/4: fp16 mma.sync GEMM, 512 threads (16 warps = 4M x 4N),
// warp tile 32x64, K-chunk 64 halfs (128B SW128 rows), 3-stage cp.async.
//   PROJ=false: GI[dir] = X @ Wih[dir]^T   (M=16384, N=1536, K=1024)
//   PROJ=true:  out = concat(Hf,Hb) @ Wproj^T, stored transposed to [B][S][E]
// SMEM: A[3][128][128B] @0 (48KB), B[3][256][128B] @48KB (96KB). Total 144KB.
// ---------------------------------------------------------------------------
#define GSMEM_BYTES 147456

template <bool PROJ>
__global__ __launch_bounds__(512, 1)
void mm_gemm_kernel(float* __restrict__ outp) {
    extern __shared__ __align__(128) char smc[];
    const uint32_t sbase = (uint32_t)__cvta_generic_to_shared(smc);
    const int tid  = threadIdx.x;
    const int lane = tid & 31;
    const int warp = tid >> 5;          // 0..15
    const int n0  = blockIdx.x * 256;
    const int m0  = blockIdx.y * 128;
    const int dir = blockIdx.z;

    const __half* __restrict__ Wg = PROJ ? g_Wproj_h : g_Wih_h[dir];

    const int wm = (warp & 3) * 32;
    const int wn = (warp >> 2) * 64;

    const int a_rr = lane & 15;
    const int a_cs = lane >> 4;
    const int b_rr = (lane & 7) | ((lane & 16) >> 1);
    const int b_cs = (lane >> 3) & 1;

    float acc[2][8][4];
    #pragma unroll
    for (int i = 0; i < 2; i++)
        #pragma unroll
        for (int j = 0; j < 8; j++)
            #pragma unroll
            for (int e = 0; e < 4; e++) acc[i][j][e] = 0.0f;

    auto stage = [&](int s, int kt) {
        #pragma unroll
        for (int q = 0; q < 2; q++) {            // A: 1024 cp16
            int id = tid + q * 512;
            int r = id >> 3, c8 = id & 7;
            const __half* src;
            if (PROJ) {
                const __half* hs = (kt < 8) ? g_Hh[0] : g_Hh[1];
                src = &hs[(size_t)(m0 + r) * H_ + (kt & 7) * 64 + c8 * 8];
            } else {
                src = &g_Xh[(size_t)(m0 + r) * DIN_ + kt * 64 + c8 * 8];
            }
            cp16s(sbase + s * 16384 + r * 128 + ((c8 ^ (r & 7)) << 4), src);
        }
        #pragma unroll
        for (int q = 0; q < 4; q++) {            // B: 2048 cp16
            int id = tid + q * 512;
            int r = id >> 3, c8 = id & 7;
            cp16s(sbase + 49152 + s * 32768 + r * 128 + ((c8 ^ (r & 7)) << 4),
                  &Wg[(size_t)(n0 + r) * 1024 + kt * 64 + c8 * 8]);
        }
    };

    stage(0, 0); cp_commit();
    stage(1, 1); cp_commit();

    for (int kt = 0; kt < 16; kt++) {
        if (kt < 15) cp_wait<1>(); else cp_wait<0>();
        __syncthreads();
        if (kt + 2 < 16) { stage((kt + 2) % 3, kt + 2); cp_commit(); }

        const int s = kt % 3;
        const uint32_t sa = sbase + s * 16384;
        const uint32_t sb = sbase + 49152 + s * 32768;

        #pragma unroll
        for (int k16 = 0; k16 < 4; k16++) {
            uint32_t a[2][4];
            #pragma unroll
            for (int mi = 0; mi < 2; mi++) {
                int rr = wm + 16 * mi + a_rr;
                ldsm4(a[mi][0], a[mi][1], a[mi][2], a[mi][3],
                      sa + rr * 128 + (((2 * k16 + a_cs) ^ (rr & 7)) << 4));
            }
            #pragma unroll
            for (int g2 = 0; g2 < 4; g2++) {
                int rr = wn + 16 * g2 + b_rr;
                uint32_t b0, b1, b2, b3;
                ldsm4(b0, b1, b2, b3,
                      sb + rr * 128 + (((2 * k16 + b_cs) ^ (rr & 7)) << 4));
                #pragma unroll
                for (int mi = 0; mi < 2; mi++) {
                    mma16(acc[mi][2 * g2], a[mi], b0, b1);
                    mma16(acc[mi][2 * g2 + 1], a[mi], b2, b3);
                }
            }
        }
    }

    const int re = lane >> 2, ce = 2 * (lane & 3);
    #pragma unroll
    for (int mi = 0; mi < 2; mi++) {
        #pragma unroll
        for (int j = 0; j < 8; j++) {
            int row = m0 + wm + 16 * mi + re;
            int col = n0 + wn + 8 * j + ce;
            if (!PROJ) {
                float* C = g_GI[dir];
                *(float2*)&C[(size_t)row * H3_ + col] =
                    make_float2(acc[mi][j][0], acc[mi][j][1]);
                *(float2*)&C[(size_t)(row + 8) * H3_ + col] =
                    make_float2(acc[mi][j][2], acc[mi][j][3]);
            } else {
                int r1 = row, r2 = row + 8;
                size_t o1 = ((size_t)(r1 & 255) * S_ + (r1 >> 8)) * E_ + col;
                size_t o2 = ((size_t)(r2 & 255) * S_ + (r2 >> 8)) * E_ + col;
                *(float2*)&outp[o1] = make_float2(acc[mi][j][0], acc[mi][j][1]);
                *(float2*)&outp[o2] = make_float2(acc[mi][j][2], acc[mi][j][3]);
            }
        }
    }
}

// ---------------------------------------------------------------------------
// Kernel 3: PERSISTENT bidirectional GRU recurrence, fp16 GEMM.
// 128 CTAs x 512 threads (16 warps = 8 M-slices x 2 K-halves).
// K-chunk 64 halfs; 4 chunks per K-half; 3-stage cp.async, 1 sync/iter.
// Split-phase group barrier with next-step GI prefetch under the wait.
// SMEM bytes: WSM [8kc][48][128B] = 49152 @0 | ASM 3x2x128x128B = 98304 @49152
//             GH (fp32, 2x128x48 = 49152B) overlays ASM. Total 147456 B.
// ---------------------------------------------------------------------------
#define WSM_OFF 0
#define ASM_OFF 49152
#define GH_OFF  49152
#define PSMEM_BYTES 147456

__global__ __launch_bounds__(512, 1)
void gru_persistent_kernel(const float* __restrict__ Whh_f,
                           const float* __restrict__ Whh_b,
                           const float* __restrict__ bih_f,
                           const float* __restrict__ bhh_f,
                           const float* __restrict__ bih_b,
                           const float* __restrict__ bhh_b) {
    extern __shared__ __align__(128) char smc[];
    const uint32_t sbase = (uint32_t)__cvta_generic_to_shared(smc);
    float* GH = (float*)(smc + GH_OFF);

    const int cta = blockIdx.x;
    const int dir = cta >> 6;
    const int rem = cta & 63;
    const int j0  = (rem >> 1) * 16;
    const int b0  = (rem & 1) * 128;
    const int grp = (dir << 1) | (rem & 1);
    volatile unsigned* bar_cnt = &g_bar_cnt[grp * 32];
    volatile unsigned* bar_gen = &g_bar_gen[grp * 32];

    const int tid  = threadIdx.x;
    const int lane = tid & 31;
    const int warp = tid >> 5;         // 0..15
    const int kh   = warp >> 3;        // K-half 0/1
    const int wm16 = (warp & 7) * 16;  // 16-row M slice

    const int a_rr = lane & 15;
    const int a_cs = lane >> 4;
    const int b_rr = (lane & 7) | ((lane & 16) >> 1);
    const int b_cs = (lane >> 3) & 1;

    const float* __restrict__ Whh = dir ? Whh_b : Whh_f;
    const float* __restrict__ bih = dir ? bih_b : bih_f;
    const float* __restrict__ bhh = dir ? bhh_b : bhh_f;
    float*  __restrict__ GI  = g_GI[dir];
    float*  __restrict__ Hst = g_Hbuf[dir];
    __half* __restrict__ Hhd = g_Hh[dir];

    const int jc = j0 + (tid & 15);
    const int rbase = tid >> 4;        // 0..31; epilogue rows rbase + 32*k
    const float bias_r  = bih[jc]           + bhh[jc];
    const float bias_z  = bih[H_ + jc]      + bhh[H_ + jc];
    const float bias_in = bih[2 * H_ + jc];
    const float bias_hn = bhh[2 * H_ + jc];

    // Load Whh slice into SMEM as fp16, k-chunked SW128 layout:
    // [kc 0..7][row 0..47 (= gate*16+jl)][64 halfs = 128B].
    for (int idx = tid; idx < 48 * 64; idx += 512) {
        int row = idx >> 6;          // 0..47
        int c   = idx & 63;          // 8-half chunk within the 512 k-cols
        int kc = c >> 3, c8 = c & 7;
        int g = row >> 4, jl = row & 15;
        const float4* src = (const float4*)
            &Whh[((size_t)(g * H_ + j0 + jl)) * H_ + c * 8];
        uint2 lo = f4h(src[0]);
        uint2 hi = f4h(src[1]);
        uint4 w = make_uint4(lo.x, lo.y, hi.x, hi.y);
        *(uint4*)(smc + WSM_OFF + (kc * 48 + row) * 128 + ((c8 ^ (row & 7)) << 4)) = w;
    }
    __syncthreads();

    // Prefetch GI for tau = 0.
    float pir[4], piz[4], pinn[4];
    {
        const int rs0 = dir ? (S_ - 1) : 0;
        const size_t gi_base = (size_t)(rs0 * B_) * H3_;
        #pragma unroll
        for (int k = 0; k < 4; k++) {
            size_t girow = gi_base + (size_t)(b0 + rbase + 32 * k) * H3_;
            pir[k]  = GI[girow + jc];
            piz[k]  = GI[girow + H_ + jc];
            pinn[k] = GI[girow + 2 * H_ + jc];
        }
    }

    for (int tau = 0; tau < S_; tau++) {
        const int row_store = dir ? (S_ - 1 - tau) : tau;
        const int row_prev  = dir ? (S_ - tau)     : (tau - 1);
        const float* __restrict__ hprev =
            (tau > 0) ? &Hst[(size_t)row_prev * B_ * H_] : nullptr;

        // hp prefetch (independent LDGs, hidden by the GEMM below)
        float php[4];
        #pragma unroll
        for (int k = 0; k < 4; k++)
            php[k] = (tau > 0) ? hprev[(size_t)(b0 + rbase + 32 * k) * H_ + jc] : 0.0f;

        if (tau > 0) {
            const __half* __restrict__ hh = &Hhd[(size_t)row_prev * B_ * H_];

            float acc[6][4];
            #pragma unroll
            for (int j = 0; j < 6; j++)
                #pragma unroll
                for (int e = 0; e < 4; e++) acc[j][e] = 0.0f;

            auto stage = [&](int s, int i) {
                #pragma unroll
                for (int q = 0; q < 4; q++) {
                    int id = tid + q * 512;       // 0..2047
                    int khs = id >> 10;           // 0/1
                    int r = (id >> 3) & 127, c8 = id & 7;
                    int kc = khs * 4 + i;
                    cp16s(sbase + ASM_OFF + (s * 2 + khs) * 16384 + r * 128
                              + ((c8 ^ (r & 7)) << 4),
                          &hh[(size_t)(b0 + r) * H_ + kc * 64 + c8 * 8]);
                }
            };

            stage(0, 0); cp_commit();
            stage(1, 1); cp_commit();

            for (int i = 0; i < 4; i++) {
                if (i < 3) cp_wait<1>(); else cp_wait<0>();
                __syncthreads();
                if (i + 2 < 4) { stage((i + 2) % 3, i + 2); cp_commit(); }

                const int sbuf = i % 3;
                const uint32_t sa = sbase + ASM_OFF + (sbuf * 2 + kh) * 16384;
                const int kc = kh * 4 + i;
                const uint32_t wb = sbase + WSM_OFF + kc * 48 * 128;

                #pragma unroll
                for (int k16 = 0; k16 < 4; k16++) {
                    uint32_t a[4];
                    int rr = wm16 + a_rr;
                    ldsm4(a[0], a[1], a[2], a[3],
                          sa + rr * 128 + (((2 * k16 + a_cs) ^ (rr & 7)) << 4));
                    #pragma unroll
                    for (int g2 = 0; g2 < 3; g2++) {
                        int br = 16 * g2 + b_rr;
                        uint32_t bb0, bb1, bb2, bb3;
                        ldsm4(bb0, bb1, bb2, bb3,
                              wb + br * 128 + (((2 * k16 + b_cs) ^ (br & 7)) << 4));
                        mma16(acc[2 * g2], a, bb0, bb1);
                        mma16(acc[2 * g2 + 1], a, bb2, bb3);
                    }
                }
            }
            __syncthreads();   // all reads of ASM done before GH overlay writes

            // Write partials to GH[kh] (overlays ASM stages)
            const int re = lane >> 2, ce = 2 * (lane & 3);
            #pragma unroll
            for (int j = 0; j < 6; j++) {
                int row = wm16 + re;
                int col = 8 * j + ce;
                int off = kh * 6144 + row * 48 + col;
                *(float2*)&GH[off] = make_float2(acc[j][0], acc[j][1]);
                *(float2*)&GH[off + 8 * 48] = make_float2(acc[j][2], acc[j][3]);
            }
            __syncthreads();
        }

        // Gate epilogue: 128 rows x 16 j, 4 per thread; operands prefetched.
        const size_t h_base = (size_t)(row_store * B_) * H_;
        const int c = tid & 15;
        #pragma unroll
        for (int k = 0; k < 4; k++) {
            int r = rbase + 32 * k;
            int bb = b0 + r;
            float hr_ = 0.f, hz = 0.f, hn = 0.f;
            if (tau > 0) {
                int base = r * 48;
                hr_ = GH[base + c]      + GH[base + 6144 + c];
                hz  = GH[base + 16 + c] + GH[base + 6144 + 16 + c];
                hn  = GH[base + 32 + c] + GH[base + 6144 + 32 + c];
            }
            float rg = 0.5f + 0.5f * tanhax(0.5f * (pir[k] + hr_ + bias_r));
            float zg = 0.5f + 0.5f * tanhax(0.5f * (piz[k] + hz + bias_z));
            float ng = tanhax(pinn[k] + bias_in + rg * (hn + bias_hn));
            float hnew = fmaf(zg, php[k] - ng, ng);
            Hst[h_base + (size_t)bb * H_ + jc] = hnew;
            Hhd[h_base + (size_t)bb * H_ + jc] = __float2half_rn(hnew);
        }

        // Split-phase barrier: arrive -> prefetch next GI -> wait.
        if (tau != S_ - 1) {
            __syncthreads();           // all stores issued
            unsigned g = 0, a = 0;
            if (tid == 0) {
                __threadfence();
                g = *bar_gen;
                a = atomicAdd((unsigned*)bar_cnt, 1u);
                if (a == 31) {
                    *bar_cnt = 0;
                    __threadfence();
                    atomicAdd((unsigned*)bar_gen, 1u);
                }
            }
            // Prefetch GI for tau+1 (independent of h) under the barrier wait
            {
                const int rs1 = dir ? (S_ - 2 - tau) : (tau + 1);
                const size_t gi_base = (size_t)(rs1 * B_) * H3_;
                #pragma unroll
                for (int k = 0; k < 4; k++) {
                    size_t girow = gi_base + (size_t)(b0 + rbase + 32 * k) * H3_;
                    pir[k]  = GI[girow + jc];
                    piz[k]  = GI[girow + H_ + jc];
                    pinn[k] = GI[girow + 2 * H_ + jc];
                }
            }
            if (tid == 0 && a != 31) {
                while (*bar_gen == g) { }
                __threadfence();
            }
            __syncthreads();
        }
    }
}

// ---------------------------------------------------------------------------
extern "C" void kernel_launch(void* const* d_in, const int* in_sizes, int n_in,
                              void* d_out, int out_size) {
    const int*   slot_ids = (const int*)d_in[0];
    const float* value    = (const float*)d_in[1];
    const float* table    = (const float*)d_in[2];
    const float* Wih_f    = (const float*)d_in[3];
    const float* Whh_f    = (const float*)d_in[4];
    const float* bih_f    = (const float*)d_in[5];
    const float* bhh_f    = (const float*)d_in[6];
    const float* Wih_b    = (const float*)d_in[7];
    const float* Whh_b    = (const float*)d_in[8];
    const float* bih_b    = (const float*)d_in[9];
    const float* bhh_b    = (const float*)d_in[10];
    const float* Wproj    = (const float*)d_in[11];
    float* out = (float*)d_out;

    cudaFuncSetAttribute(mm_gemm_kernel<false>,
                         cudaFuncAttributeMaxDynamicSharedMemorySize, GSMEM_BYTES);
    cudaFuncSetAttribute(mm_gemm_kernel<true>,
                         cudaFuncAttributeMaxDynamicSharedMemorySize, GSMEM_BYTES);
    cudaFuncSetAttribute(gru_persistent_kernel,
                         cudaFuncAttributeMaxDynamicSharedMemorySize, PSMEM_BYTES);

    round_weights_kernel<<<(H3_ * DIN_ / 4 + 255) / 256, 256>>>(
        (const float4*)Wih_f, (const float4*)Wih_b, (const float4*)Wproj);
    build_x_kernel<<<M_, 256>>>(slot_ids, value, table);
    mm_gemm_kernel<false><<<dim3(H3_ / 256, M_ / 128, 2), 512, GSMEM_BYTES>>>(nullptr);
    gru_persistent_kernel<<<128, 512, PSMEM_BYTES>>>(
        Whh_f, Whh_b, bih_f, bhh_f, bih_b, bhh_b);
    mm_gemm_kernel<true><<<dim3(E_ / 256, M_ / 128, 1), 512, GSMEM_BYTES>>>(out);
}

// round 13
// speedup vs baseline: 6.4166x; 1.0096x over previous
#include <cuda_runtime.h>
#include <cuda_fp16.h>
#include <cstdint>

// Problem constants
#define B_    256
#define S_    64
#define DIN_  1024
#define H_    512
#define H3_   1536
#define E_    512
#define M_    (S_ * B_)   // 16384 rows (t*B + b)

// Scratch (device globals; no runtime allocation allowed)
__device__ __half g_Xh[(size_t)M_ * DIN_];        // fp16 inputs for GEMM
__device__ __half g_Wih_h[2][(size_t)H3_ * DIN_]; // fp16 weights
__device__ __half g_Wproj_h[(size_t)E_ * 2 * H_];
__device__ float  g_GI[2][(size_t)M_ * H3_];      // input-transform, fp32
__device__ __half g_Hh[2][(size_t)M_ * H_];       // fp16 GRU outputs (GEMM + proj input)

// Group barrier state: 4 groups (dir x b-half), 32 CTAs each. Padded lines.
__device__ volatile unsigned g_bar_cnt[4 * 32];
__device__ volatile unsigned g_bar_gen[4 * 32];

// ---------------- low-level helpers ----------------
__device__ __forceinline__ void cp16s(uint32_t s, const void* g) {
    asm volatile("cp.async.cg.shared.global [%0], [%1], 16;\n" :: "r"(s), "l"(g));
}
__device__ __forceinline__ void cp_commit() {
    asm volatile("cp.async.commit_group;\n" ::);
}
template <int N> __device__ __forceinline__ void cp_wait() {
    asm volatile("cp.async.wait_group %0;\n" :: "n"(N));
}

__device__ __forceinline__ uint2 f4h(float4 v) {
    __half2 a = __floats2half2_rn(v.x, v.y);
    __half2 b = __floats2half2_rn(v.z, v.w);
    uint2 r;
    r.x = *reinterpret_cast<uint32_t*>(&a);
    r.y = *reinterpret_cast<uint32_t*>(&b);
    return r;
}

__device__ __forceinline__ float tanhax(float x) {
    float y;
    asm("tanh.approx.f32 %0, %1;" : "=f"(y) : "f"(x));
    return y;
}

__device__ __forceinline__ void ldsm4(uint32_t& r0, uint32_t& r1, uint32_t& r2,
                                      uint32_t& r3, uint32_t addr) {
    asm volatile("ldmatrix.sync.aligned.m8n8.x4.shared.b16 {%0,%1,%2,%3}, [%4];"
                 : "=r"(r0), "=r"(r1), "=r"(r2), "=r"(r3) : "r"(addr));
}

// fp16 MMA, fp32 accumulate: D[16x8] += A[16x16] * B[16x8]
__device__ __forceinline__ void mma16(float* d, const uint32_t* a,
                                      uint32_t b0, uint32_t b1) {
    asm volatile(
        "mma.sync.aligned.m16n8k16.row.col.f32.f16.f16.f32 "
        "{%0,%1,%2,%3},{%4,%5,%6,%7},{%8,%9},{%0,%1,%2,%3};"
        : "+f"(d[0]), "+f"(d[1]), "+f"(d[2]), "+f"(d[3])
        : "r"(a[0]), "r"(a[1]), "r"(a[2]), "r"(a[3]), "r"(b0), "r"(b1));
}

// ---------------------------------------------------------------------------
// Kernel 0: convert weights to fp16 scratch
// ---------------------------------------------------------------------------
__global__ void round_weights_kernel(const float4* __restrict__ wf,
                                     const float4* __restrict__ wb,
                                     const float4* __restrict__ wp) {
    const int NW = H3_ * DIN_ / 4;   // 393216
    const int NP = E_ * 2 * H_ / 4;  // 131072
    int i = blockIdx.x * blockDim.x + threadIdx.x;
    if (i < NW) {
        ((uint2*)g_Wih_h[0])[i] = f4h(wf[i]);
        ((uint2*)g_Wih_h[1])[i] = f4h(wb[i]);
        if (i < NP) ((uint2*)g_Wproj_h)[i] = f4h(wp[i]);
    }
}

// ---------------------------------------------------------------------------
// Kernel 1: gather slot embedding + concat value embeds -> Xh (fp16)
// ---------------------------------------------------------------------------
__global__ void build_x_kernel(const int* __restrict__ slot_ids,
                               const float* __restrict__ value_embeds,
                               const float* __restrict__ embed_table) {
    int m = blockIdx.x;            // = t*B + b
    int t = m >> 8;
    int b = m & 255;
    int c4 = threadIdx.x;          // float4 column 0..255
    float4 v;
    if (c4 < 64) {
        int sid = slot_ids[b * S_ + t];
        v = ((const float4*)embed_table)[(size_t)sid * 64 + c4];
    } else {
        v = ((const float4*)value_embeds)[(size_t)(b * S_ + t) * 192 + (c4 - 64)];
    }
    ((uint2*)g_Xh)[(size_t)m * 256 + c4] = f4h(v);
}

// ---------------------------------------------------------------------------
// Kernel 2/4: fp16 mma.sync GEMM, 512 threads (16 warps = 4M x 4N),
// warp tile 32x64, K-chunk 64 halfs (128B SW128 rows), 3-stage cp.async.
//   PROJ=false: GI[dir] = X @ Wih[dir]^T   (M=16384, N=1536, K=1024)
//   PROJ=true:  out = concat(Hf,Hb) @ Wproj^T, stored transposed to [B][S][E]
// SMEM: A[3][128][128B] @0 (48KB), B[3][256][128B] @48KB (96KB). Total 144KB.
// ---------------------------------------------------------------------------
#define GSMEM_BYTES 147456

template <bool PROJ>
__global__ __launch_bounds__(512, 1)
void mm_gemm_kernel(float* __restrict__ outp) {
    extern __shared__ __align__(128) char smc[];
    const uint32_t sbase = (uint32_t)__cvta_generic_to_shared(smc);
    const int tid  = threadIdx.x;
    const int lane = tid & 31;
    const int warp = tid >> 5;          // 0..15
    const int n0  = blockIdx.x * 256;
    const int m0  = blockIdx.y * 128;
    const int dir = blockIdx.z;

    const __half* __restrict__ Wg = PROJ ? g_Wproj_h : g_Wih_h[dir];

    const int wm = (warp & 3) * 32;
    const int wn = (warp >> 2) * 64;

    const int a_rr = lane & 15;
    const int a_cs = lane >> 4;
    const int b_rr = (lane & 7) | ((lane & 16) >> 1);
    const int b_cs = (lane >> 3) & 1;

    float acc[2][8][4];
    #pragma unroll
    for (int i = 0; i < 2; i++)
        #pragma unroll
        for (int j = 0; j < 8; j++)
            #pragma unroll
            for (int e = 0; e < 4; e++) acc[i][j][e] = 0.0f;

    auto stage = [&](int s, int kt) {
        #pragma unroll
        for (int q = 0; q < 2; q++) {            // A: 1024 cp16
            int id = tid + q * 512;
            int r = id >> 3, c8 = id & 7;
            const __half* src;
            if (PROJ) {
                const __half* hs = (kt < 8) ? g_Hh[0] : g_Hh[1];
                src = &hs[(size_t)(m0 + r) * H_ + (kt & 7) * 64 + c8 * 8];
            } else {
                src = &g_Xh[(size_t)(m0 + r) * DIN_ + kt * 64 + c8 * 8];
            }
            cp16s(sbase + s * 16384 + r * 128 + ((c8 ^ (r & 7)) << 4), src);
        }
        #pragma unroll
        for (int q = 0; q < 4; q++) {            // B: 2048 cp16
            int id = tid + q * 512;
            int r = id >> 3, c8 = id & 7;
            cp16s(sbase + 49152 + s * 32768 + r * 128 + ((c8 ^ (r & 7)) << 4),
                  &Wg[(size_t)(n0 + r) * 1024 + kt * 64 + c8 * 8]);
        }
    };

    stage(0, 0); cp_commit();
    stage(1, 1); cp_commit();

    for (int kt = 0; kt < 16; kt++) {
        if (kt < 15) cp_wait<1>(); else cp_wait<0>();
        __syncthreads();
        if (kt + 2 < 16) { stage((kt + 2) % 3, kt + 2); cp_commit(); }

        const int s = kt % 3;
        const uint32_t sa = sbase + s * 16384;
        const uint32_t sb = sbase + 49152 + s * 32768;

        #pragma unroll
        for (int k16 = 0; k16 < 4; k16++) {
            uint32_t a[2][4];
            #pragma unroll
            for (int mi = 0; mi < 2; mi++) {
                int rr = wm + 16 * mi + a_rr;
                ldsm4(a[mi][0], a[mi][1], a[mi][2], a[mi][3],
                      sa + rr * 128 + (((2 * k16 + a_cs) ^ (rr & 7)) << 4));
            }
            #pragma unroll
            for (int g2 = 0; g2 < 4; g2++) {
                int rr = wn + 16 * g2 + b_rr;
                uint32_t b0, b1, b2, b3;
                ldsm4(b0, b1, b2, b3,
                      sb + rr * 128 + (((2 * k16 + b_cs) ^ (rr & 7)) << 4));
                #pragma unroll
                for (int mi = 0; mi < 2; mi++) {
                    mma16(acc[mi][2 * g2], a[mi], b0, b1);
                    mma16(acc[mi][2 * g2 + 1], a[mi], b2, b3);
                }
            }
        }
    }

    const int re = lane >> 2, ce = 2 * (lane & 3);
    #pragma unroll
    for (int mi = 0; mi < 2; mi++) {
        #pragma unroll
        for (int j = 0; j < 8; j++) {
            int row = m0 + wm + 16 * mi + re;
            int col = n0 + wn + 8 * j + ce;
            if (!PROJ) {
                float* C = g_GI[dir];
                *(float2*)&C[(size_t)row * H3_ + col] =
                    make_float2(acc[mi][j][0], acc[mi][j][1]);
                *(float2*)&C[(size_t)(row + 8) * H3_ + col] =
                    make_float2(acc[mi][j][2], acc[mi][j][3]);
            } else {
                int r1 = row, r2 = row + 8;
                size_t o1 = ((size_t)(r1 & 255) * S_ + (r1 >> 8)) * E_ + col;
                size_t o2 = ((size_t)(r2 & 255) * S_ + (r2 >> 8)) * E_ + col;
                *(float2*)&outp[o1] = make_float2(acc[mi][j][0], acc[mi][j][1]);
                *(float2*)&outp[o2] = make_float2(acc[mi][j][2], acc[mi][j][3]);
            }
        }
    }
}

// ---------------------------------------------------------------------------
// Kernel 3: PERSISTENT bidirectional GRU recurrence, fp16 GEMM.
// 128 CTAs x 512 threads (16 warps = 8 M-slices x 2 K-halves).
// h fp32 trajectory lives ENTIRELY in registers (php[4] per thread; a thread's
// epilogue (row, col) set equals its next-step hp needs). Only fp16 h is
// written to global (GEMM A + projection input).
// A tile (128x512 fp16 = 128KB) staged single-buffered in two commits
// interleaved across K-halves: commit1 = kc{0,1,4,5}, commit2 = kc{2,3,6,7};
// compute pass 0 (chunks 0-1 of each kh) overlaps commit2 arrival.
// SMEM: WSM [8kc][48][128B] = 48KB @0 | ASM [8kc][128][128B] = 128KB @49152.
// GH (fp32, 2x128x48 = 48KB) overlays ASM. Total 180224 B.
// ---------------------------------------------------------------------------
#define WSM_OFF 0
#define ASM_OFF 49152
#define GH_OFF  49152
#define PSMEM_BYTES (49152 + 131072)

__global__ __launch_bounds__(512, 1)
void gru_persistent_kernel(const float* __restrict__ Whh_f,
                           const float* __restrict__ Whh_b,
                           const float* __restrict__ bih_f,
                           const float* __restrict__ bhh_f,
                           const float* __restrict__ bih_b,
                           const float* __restrict__ bhh_b) {
    extern __shared__ __align__(128) char smc[];
    const uint32_t sbase = (uint32_t)__cvta_generic_to_shared(smc);
    float* GH = (float*)(smc + GH_OFF);

    const int cta = blockIdx.x;
    const int dir = cta >> 6;
    const int rem = cta & 63;
    const int j0  = (rem >> 1) * 16;
    const int b0  = (rem & 1) * 128;
    const int grp = (dir << 1) | (rem & 1);
    volatile unsigned* bar_cnt = &g_bar_cnt[grp * 32];
    volatile unsigned* bar_gen = &g_bar_gen[grp * 32];

    const int tid  = threadIdx.x;
    const int lane = tid & 31;
    const int warp = tid >> 5;         // 0..15
    const int kh   = warp >> 3;        // K-half 0/1
    const int wm16 = (warp & 7) * 16;  // 16-row M slice

    const int a_rr = lane & 15;
    const int a_cs = lane >> 4;
    const int b_rr = (lane & 7) | ((lane & 16) >> 1);
    const int b_cs = (lane >> 3) & 1;

    const float* __restrict__ Whh = dir ? Whh_b : Whh_f;
    const float* __restrict__ bih = dir ? bih_b : bih_f;
    const float* __restrict__ bhh = dir ? bhh_b : bhh_f;
    float*  __restrict__ GI  = g_GI[dir];
    __half* __restrict__ Hhd = g_Hh[dir];

    const int jc = j0 + (tid & 15);
    const int rbase = tid >> 4;        // 0..31; epilogue rows rbase + 32*k
    const float bias_r  = bih[jc]           + bhh[jc];
    const float bias_z  = bih[H_ + jc]      + bhh[H_ + jc];
    const float bias_in = bih[2 * H_ + jc];
    const float bias_hn = bhh[2 * H_ + jc];

    // Load Whh slice into SMEM as fp16, k-chunked SW128 layout:
    // [kc 0..7][row 0..47 (= gate*16+jl)][64 halfs = 128B].
    for (int idx = tid; idx < 48 * 64; idx += 512) {
        int row = idx >> 6;          // 0..47
        int c   = idx & 63;          // 8-half chunk within the 512 k-cols
        int kc = c >> 3, c8 = c & 7;
        int g = row >> 4, jl = row & 15;
        const float4* src = (const float4*)
            &Whh[((size_t)(g * H_ + j0 + jl)) * H_ + c * 8];
        uint2 lo = f4h(src[0]);
        uint2 hi = f4h(src[1]);
        uint4 w = make_uint4(lo.x, lo.y, hi.x, hi.y);
        *(uint4*)(smc + WSM_OFF + (kc * 48 + row) * 128 + ((c8 ^ (row & 7)) << 4)) = w;
    }
    __syncthreads();

    // h trajectory in registers: php[k] = h(t-1) at (b0+rbase+32k, jc). Zero-init.
    float php[4] = {0.f, 0.f, 0.f, 0.f};

    // Prefetch GI for tau = 0.
    float pir[4], piz[4], pinn[4];
    {
        const int rs0 = dir ? (S_ - 1) : 0;
        const size_t gi_base = (size_t)(rs0 * B_) * H3_;
        #pragma unroll
        for (int k = 0; k < 4; k++) {
            size_t girow = gi_base + (size_t)(b0 + rbase + 32 * k) * H3_;
            pir[k]  = GI[girow + jc];
            piz[k]  = GI[girow + H_ + jc];
            pinn[k] = GI[girow + 2 * H_ + jc];
        }
    }

    for (int tau = 0; tau < S_; tau++) {
        const int row_store = dir ? (S_ - 1 - tau) : tau;
        const int row_prev  = dir ? (S_ - tau)     : (tau - 1);

        if (tau > 0) {
            const __half* __restrict__ hh = &Hhd[(size_t)row_prev * B_ * H_];

            float acc[6][4];
            #pragma unroll
            for (int j = 0; j < 6; j++)
                #pragma unroll
                for (int e = 0; e < 4; e++) acc[j][e] = 0.0f;

            // Stage whole A tile in two interleaved commits.
            auto stageHalf = [&](int half) {
                const int ksel0 = half ? 2 : 0;
                #pragma unroll
                for (int q = 0; q < 8; q++) {
                    int id = tid + q * 512;       // 0..4095
                    int gk = id >> 11;            // which kh group
                    int ii = (id >> 10) & 1;      // chunk within pair
                    int kc = gk * 4 + ksel0 + ii;
                    int r = (id >> 3) & 127, c8 = id & 7;
                    cp16s(sbase + ASM_OFF + kc * 16384 + r * 128
                              + ((c8 ^ (r & 7)) << 4),
                          &hh[(size_t)(b0 + r) * H_ + kc * 64 + c8 * 8]);
                }
                cp_commit();
            };
            stageHalf(0);
            stageHalf(1);

            cp_wait<1>();
            __syncthreads();
            #pragma unroll
            for (int p = 0; p < 2; p++) {
                #pragma unroll
                for (int ii = 0; ii < 2; ii++) {
                    const int i = 2 * p + ii;
                    const int kc = kh * 4 + i;
                    const uint32_t sa = sbase + ASM_OFF + kc * 16384;
                    const uint32_t wb = sbase + WSM_OFF + kc * 48 * 128;
                    #pragma unroll
                    for (int k16 = 0; k16 < 4; k16++) {
                        uint32_t a[4];
                        int rr = wm16 + a_rr;
                        ldsm4(a[0], a[1], a[2], a[3],
                              sa + rr * 128 + (((2 * k16 + a_cs) ^ (rr & 7)) << 4));
                        #pragma unroll
                        for (int g2 = 0; g2 < 3; g2++) {
                            int br = 16 * g2 + b_rr;
                            uint32_t bb0, bb1, bb2, bb3;
                            ldsm4(bb0, bb1, bb2, bb3,
                                  wb + br * 128 + (((2 * k16 + b_cs) ^ (br & 7)) << 4));
                            mma16(acc[2 * g2], a, bb0, bb1);
                            mma16(acc[2 * g2 + 1], a, bb2, bb3);
                        }
                    }
                }
                if (p == 0) { cp_wait<0>(); __syncthreads(); }
            }
            __syncthreads();   // all ASM reads done before GH overlay writes

            // Write partials to GH[kh] (overlays ASM chunks 0-2)
            const int re = lane >> 2, ce = 2 * (lane & 3);
            #pragma unroll
            for (int j = 0; j < 6; j++) {
                int row = wm16 + re;
                int col = 8 * j + ce;
                int off = kh * 6144 + row * 48 + col;
                *(float2*)&GH[off] = make_float2(acc[j][0], acc[j][1]);
                *(float2*)&GH[off + 8 * 48] = make_float2(acc[j][2], acc[j][3]);
            }
            __syncthreads();
        }

        // Gate epilogue: 128 rows x 16 j, 4 per thread; h kept in registers.
        const size_t h_base = (size_t)(row_store * B_) * H_;
        const int c = tid & 15;
        #pragma unroll
        for (int k = 0; k < 4; k++) {
            int r = rbase + 32 * k;
            int bb = b0 + r;
            float hr_ = 0.f, hz = 0.f, hn = 0.f;
            if (tau > 0) {
                int base = r * 48;
                hr_ = GH[base + c]      + GH[base + 6144 + c];
                hz  = GH[base + 16 + c] + GH[base + 6144 + 16 + c];
                hn  = GH[base + 32 + c] + GH[base + 6144 + 32 + c];
            }
            float rg = 0.5f + 0.5f * tanhax(0.5f * (pir[k] + hr_ + bias_r));
            float zg = 0.5f + 0.5f * tanhax(0.5f * (piz[k] + hz + bias_z));
            float ng = tanhax(pinn[k] + bias_in + rg * (hn + bias_hn));
            float hnew = fmaf(zg, php[k] - ng, ng);
            php[k] = hnew;                               // fp32 trajectory in regs
            Hhd[h_base + (size_t)bb * H_ + jc] = __float2half_rn(hnew);
        }

        // Split-phase barrier: arrive -> prefetch next GI -> wait.
        if (tau != S_ - 1) {
            __syncthreads();           // all stores issued
            unsigned g = 0, a = 0;
            if (tid == 0) {
                __threadfence();
                g = *bar_gen;
                a = atomicAdd((unsigned*)bar_cnt, 1u);
                if (a == 31) {
                    *bar_cnt = 0;
                    __threadfence();
                    atomicAdd((unsigned*)bar_gen, 1u);
                }
            }
            // Prefetch GI for tau+1 (independent of h) under the barrier wait
            {
                const int rs1 = dir ? (S_ - 2 - tau) : (tau + 1);
                const size_t gi_base = (size_t)(rs1 * B_) * H3_;
                #pragma unroll
                for (int k = 0; k < 4; k++) {
                    size_t girow = gi_base + (size_t)(b0 + rbase + 32 * k) * H3_;
                    pir[k]  = GI[girow + jc];
                    piz[k]  = GI[girow + H_ + jc];
                    pinn[k] = GI[girow + 2 * H_ + jc];
                }
            }
            if (tid == 0 && a != 31) {
                while (*bar_gen == g) { }
                __threadfence();
            }
            __syncthreads();
        }
    }
}

// ---------------------------------------------------------------------------
extern "C" void kernel_launch(void* const* d_in, const int* in_sizes, int n_in,
                              void* d_out, int out_size) {
    const int*   slot_ids = (const int*)d_in[0];
    const float* value    = (const float*)d_in[1];
    const float* table    = (const float*)d_in[2];
    const float* Wih_f    = (const float*)d_in[3];
    const float* Whh_f    = (const float*)d_in[4];
    const float* bih_f    = (const float*)d_in[5];
    const float* bhh_f    = (const float*)d_in[6];
    const float* Wih_b    = (const float*)d_in[7];
    const float* Whh_b    = (const float*)d_in[8];
    const float* bih_b    = (const float*)d_in[9];
    const float* bhh_b    = (const float*)d_in[10];
    const float* Wproj    = (const float*)d_in[11];
    float* out = (float*)d_out;

    cudaFuncSetAttribute(mm_gemm_kernel<false>,
                         cudaFuncAttributeMaxDynamicSharedMemorySize, GSMEM_BYTES);
    cudaFuncSetAttribute(mm_gemm_kernel<true>,
                         cudaFuncAttributeMaxDynamicSharedMemorySize, GSMEM_BYTES);
    cudaFuncSetAttribute(gru_persistent_kernel,
                         cudaFuncAttributeMaxDynamicSharedMemorySize, PSMEM_BYTES);

    round_weights_kernel<<<(H3_ * DIN_ / 4 + 255) / 256, 256>>>(
        (const float4*)Wih_f, (const float4*)Wih_b, (const float4*)Wproj);
    build_x_kernel<<<M_, 256>>>(slot_ids, value, table);
    mm_gemm_kernel<false><<<dim3(H3_ / 256, M_ / 128, 2), 512, GSMEM_BYTES>>>(nullptr);
    gru_persistent_kernel<<<128, 512, PSMEM_BYTES>>>(
        Whh_f, Whh_b, bih_f, bhh_f, bih_b, bhh_b);
    mm_gemm_kernel<true><<<dim3(E_ / 256, M_ / 128, 1), 512, GSMEM_BYTES>>>(out);
}